// round 9
// baseline (speedup 1.0000x reference)
#include <cuda_runtime.h>
#include <cuda_bf16.h>
#include <cstdint>

// Problem constants
#define BB   4
#define NPTS 16384
#define SPTS 4096
#define C1   128
#define C2   256
#define CIN  384
#define H1   256
#define H2   128

#define NPB  64
#define NTHR 256

// ---- GEMM2 (bf16) weight layout: k32 chunks, rows 128, stride 80B ----
#define CHS  80
#define W2CB 10240

// ---- GEMM1 (int8) weight layout: 24 chunks (2 passes x 12 k32), 128 rows x 48B ----
#define W1QC 6144

__device__ __align__(16) unsigned char g_W1qh[24 * W1QC];
__device__ __align__(16) unsigned char g_W1ql[24 * W1QC];
__device__ __align__(16) unsigned char g_W2h[8 * W2CB];
__device__ __align__(16) unsigned char g_W2l[8 * W2CB];
__device__ float g_scale1[H1];
__device__ float g_b1f[H1];
__device__ float g_b2f[H2];
__device__ int   g_ni[BB * NPTS * 3];
__device__ float g_nw[BB * NPTS * 3];

// ---------------- helpers ----------------
__device__ __forceinline__ uint32_t smem_to_u32(const void* p) {
    uint32_t a;
    asm("{ .reg .u64 t; cvta.to.shared.u64 t, %1; cvt.u32.u64 %0, t; }" : "=r"(a) : "l"(p));
    return a;
}
__device__ __forceinline__ void ldsm4(uint32_t* r, uint32_t a) {
    asm volatile("ldmatrix.sync.aligned.m8n8.x4.shared.b16 {%0,%1,%2,%3}, [%4];"
                 : "=r"(r[0]), "=r"(r[1]), "=r"(r[2]), "=r"(r[3]) : "r"(a));
}
__device__ __forceinline__ void mma_bf16(float* d, const uint32_t* a, const uint32_t* b) {
    asm volatile("mma.sync.aligned.m16n8k16.row.col.f32.bf16.bf16.f32 "
                 "{%0,%1,%2,%3}, {%4,%5,%6,%7}, {%8,%9}, {%0,%1,%2,%3};"
                 : "+f"(d[0]), "+f"(d[1]), "+f"(d[2]), "+f"(d[3])
                 : "r"(a[0]), "r"(a[1]), "r"(a[2]), "r"(a[3]), "r"(b[0]), "r"(b[1]));
}
__device__ __forceinline__ void mma_s8(int* d, const uint32_t* a, const uint32_t* b) {
    asm volatile("mma.sync.aligned.m16n8k32.row.col.s32.s8.s8.s32 "
                 "{%0,%1,%2,%3}, {%4,%5,%6,%7}, {%8,%9}, {%0,%1,%2,%3};"
                 : "+r"(d[0]), "+r"(d[1]), "+r"(d[2]), "+r"(d[3])
                 : "r"(a[0]), "r"(a[1]), "r"(a[2]), "r"(a[3]), "r"(b[0]), "r"(b[1]));
}
__device__ __forceinline__ void cpa16(uint32_t dst, const void* src) {
    asm volatile("cp.async.cg.shared.global [%0], [%1], 16;" :: "r"(dst), "l"(src));
}
#define CP_COMMIT() asm volatile("cp.async.commit_group;" ::: "memory")
#define CP_WAIT0()  asm volatile("cp.async.wait_group 0;" ::: "memory")

__device__ __forceinline__ void split2(float v0, float v1, uint32_t& hi, uint32_t& lo) {
    __nv_bfloat16 h0 = __float2bfloat16(v0), h1 = __float2bfloat16(v1);
    float l0 = v0 - __bfloat162float(h0), l1 = v1 - __bfloat162float(h1);
    hi = (uint32_t)__bfloat16_as_ushort(h0) | ((uint32_t)__bfloat16_as_ushort(h1) << 16);
    lo = (uint32_t)__bfloat16_as_ushort(__float2bfloat16(l0)) |
         ((uint32_t)__bfloat16_as_ushort(__float2bfloat16(l1)) << 16);
}
__device__ __forceinline__ void pack_split4(const float* v, uint2& H, uint2& L) {
    uint32_t h0, l0, h1, l1;
    split2(v[0], v[1], h0, l0);
    split2(v[2], v[3], h1, l1);
    H = make_uint2(h0, h1);
    L = make_uint2(l0, l1);
}
// int8 dual-plane quant of 4 floats, fixed scale 6.0
__device__ __forceinline__ void quant4(const float* a, uint32_t& H, uint32_t& L) {
    uint32_t h = 0, l = 0;
#pragma unroll
    for (int j = 0; j < 4; j++) {
        float x = fminf(fmaxf(a[j], -6.f), 6.f);
        int qh = __float2int_rn(x * (127.f / 6.f));
        float r = x - (float)qh * (6.f / 127.f);
        int ql = __float2int_rn(r * (16129.f / 6.f));
        h |= ((uint32_t)qh & 255u) << (8 * j);
        l |= ((uint32_t)ql & 255u) << (8 * j);
    }
    H = h; L = l;
}

// ---------------- kernel A: prep weights ----------------
__global__ void prep_kernel(const float* __restrict__ W1, const float* __restrict__ b1,
                            const float* __restrict__ g1, const float* __restrict__ be1,
                            const float* __restrict__ m1, const float* __restrict__ v1,
                            const float* __restrict__ W2, const float* __restrict__ b2,
                            const float* __restrict__ g2, const float* __restrict__ be2,
                            const float* __restrict__ m2, const float* __restrict__ v2) {
    int idx = blockIdx.x * blockDim.x + threadIdx.x;
    int stride = gridDim.x * blockDim.x;

    // W1 -> int8 dual-plane, per-row exact scale
    for (int o = idx; o < H1; o += stride) {
        float a = g1[o] * rsqrtf(v1[o] + 1e-5f);
        float mx = 1e-20f;
        for (int k = 0; k < CIN; k++) mx = fmaxf(mx, fabsf(W1[o * CIN + k] * a));
        float sB = mx / 127.f;
        g_scale1[o] = 6.f * mx / 16129.f;
        g_b1f[o] = (b1[o] - m1[o]) * a + be1[o];
        int np = o >> 7, ro = o & 127;
        for (int k = 0; k < CIN; k++) {
            float w = W1[o * CIN + k] * a;
            int ph = __float2int_rn(w / sB);
            float r = w - (float)ph * sB;
            int pl = __float2int_rn(r * 127.f / sB);
            int g = np * 12 + (k >> 5);
            size_t off = (size_t)g * W1QC + ro * 48 + (k & 31);
            ((char*)g_W1qh)[off] = (char)ph;
            ((char*)g_W1ql)[off] = (char)pl;
        }
    }
    // W2 -> bf16 hi/lo, k32 chunks, stride 80B
    for (int g = idx; g < 128 * 64; g += stride) {
        int o = g / 64, k0 = (g % 64) * 4;
        float a = g2[o] * rsqrtf(v2[o] + 1e-5f);
        float vv[4];
#pragma unroll
        for (int j = 0; j < 4; j++) vv[j] = W2[o * H1 + k0 + j] * a;
        uint2 H, L; pack_split4(vv, H, L);
        int chunk = k0 >> 5, kc = k0 & 31;
        size_t off = (size_t)chunk * W2CB + o * CHS + kc * 2;
        *(uint2*)(g_W2h + off) = H;
        *(uint2*)(g_W2l + off) = L;
    }
    for (int o = idx; o < H2; o += stride) {
        float a = g2[o] * rsqrtf(v2[o] + 1e-5f);
        g_b2f[o] = (b2[o] - m2[o]) * a + be2[o];
    }
}

// ---------------- kernel B: exact 3-NN (unchanged) ----------------
__global__ void __launch_bounds__(256) nn_kernel(const float* __restrict__ xyz1,
                                                 const float* __restrict__ xyz2) {
    extern __shared__ float4 sc[];
    const int b = blockIdx.y;
    const int n = blockIdx.x * 256 + threadIdx.x;

    const float* x2 = xyz2 + b * SPTS * 3;
    for (int s = threadIdx.x; s < SPTS; s += 256) {
        float x = x2[s * 3 + 0], y = x2[s * 3 + 1], z = x2[s * 3 + 2];
        sc[s] = make_float4(fmaf(x, x, fmaf(y, y, z * z)), -2.f * x, -2.f * y, -2.f * z);
    }
    __syncthreads();

    const float* qq = xyz1 + (b * NPTS + n) * 3;
    const float qx = qq[0], qy = qq[1], qz = qq[2];

    const float INF = __int_as_float(0x7f800000);
    float d0 = INF, d1 = INF, d2 = INF;
    int i0 = 0, i1 = 0, i2 = 0;

#pragma unroll 4
    for (int s = 0; s < SPTS; s++) {
        float4 c = sc[s];
        float t = fmaf(c.y, qx, c.x);
        t = fmaf(c.z, qy, t);
        t = fmaf(c.w, qz, t);
        if (t < d2) {
            if (t < d1) {
                d2 = d1; i2 = i1;
                if (t < d0) { d1 = d0; i1 = i0; d0 = t; i0 = s; }
                else        { d1 = t;  i1 = s; }
            } else { d2 = t; i2 = s; }
        }
    }

    const float qn = fmaf(qx, qx, fmaf(qy, qy, qz * qz));
    float r0 = 1.f / ((d0 + qn) + 1e-8f);
    float r1 = 1.f / ((d1 + qn) + 1e-8f);
    float r2 = 1.f / ((d2 + qn) + 1e-8f);
    float inv = 1.f / (r0 + r1 + r2);

    const int base = (b * NPTS + n) * 3;
    g_ni[base + 0] = i0; g_ni[base + 1] = i1; g_ni[base + 2] = i2;
    g_nw[base + 0] = r0 * inv; g_nw[base + 1] = r1 * inv; g_nw[base + 2] = r2 * inv;
}

// ---------------- kernel C: int8 GEMM1 + bf16 GEMM2, 2 blocks/SM ----------------
// SMEM map (110592 B total):
//  A1 int8:  hi [0,25600) lo [25600,51200)  stride 400, resident all K
//  B1 int8:  2 bufs @51200, each (hi 6144 | lo 6144), stride 48
//  H1a (cols 0-127 of h1, bf16):  hi @75776 lo @93184, stride 272   (disjoint, written pass0)
//  H1b (cols 128-255):            hi @0     lo @17408, stride 272   (written after GEMM1)
//  B2 bf16:  2 bufs @34816, each (hi 10240 | lo 10240), stride 80   (after GEMM1)
#define A1_ST   400
#define A1L_OFF 25600
#define B1_OFF  51200
#define B1_BUF  12288
#define B1_LO   6144
#define B1_ST   48
#define H1_ST   272
#define H1A_HI  75776
#define H1B_HI  0
#define H1_LO   17408
#define B2_OFF  34816
#define B2_BUF  20480
#define B2_LO   10240
#define SMEM_BYTES 110592

__global__ void __launch_bounds__(NTHR, 2) fused_kernel(const float* __restrict__ feat1,
                                                        const float* __restrict__ feat2,
                                                        float* __restrict__ out) {
    extern __shared__ __align__(128) char sm[];
    const uint32_t sb = smem_to_u32(sm);
    const int tid  = threadIdx.x;
    const int lane = tid & 31;
    const int wid  = tid >> 5;
    const int b    = blockIdx.y;
    const int n0g  = blockIdx.x * NPB;

    // producer mapping: 4 threads per point, 96 channels each
    const int p = tid >> 2;
    const int q = tid & 3;
    const int nbase = (b * NPTS + n0g + p) * 3;
    const int j0 = g_ni[nbase], j1 = g_ni[nbase + 1], j2 = g_ni[nbase + 2];
    const float w0 = g_nw[nbase], w1 = g_nw[nbase + 1], w2 = g_nw[nbase + 2];

    // ldmatrix decomposition
    const int r8 = lane & 7;
    const int g4 = lane >> 3;
    const int gm = (g4 & 1) << 3;
    const int gk = (g4 >> 1) << 3;

    // warp tiles: M64 = 4 rows of 16 (wid>>1), N halves (wid&1)
    const int m0  = (wid >> 1) * 16;
    const int nw0 = (wid & 1) * 64;   // within current 128-col pass (GEMM1) / N128 (GEMM2)

    // ---- issue B1 chunk 0 prefetch before producing A ----
    {
        const uint32_t dH = sb + B1_OFF;
        for (int i = tid * 16; i < B1_LO; i += NTHR * 16) {
            cpa16(dH + i, g_W1qh + i);
            cpa16(dH + B1_LO + i, g_W1ql + i);
        }
        CP_COMMIT();
    }

    // ---- producer: fill resident int8 A planes (64 x 384 + interp) ----
#pragma unroll 4
    for (int i = 0; i < 24; i++) {
        const int c = q * 96 + i * 4;
        float v[4];
        if (c < C1) {
            float4 x = __ldg((const float4*)(feat1 + ((size_t)(b * NPTS + n0g + p)) * C1 + c));
            v[0] = x.x; v[1] = x.y; v[2] = x.z; v[3] = x.w;
        } else {
            const int c2 = c - C1;
            float4 a0 = __ldg((const float4*)(feat2 + ((size_t)b * SPTS + j0) * C2 + c2));
            float4 b0 = __ldg((const float4*)(feat2 + ((size_t)b * SPTS + j1) * C2 + c2));
            float4 c0 = __ldg((const float4*)(feat2 + ((size_t)b * SPTS + j2) * C2 + c2));
            v[0] = fmaf(w0, a0.x, fmaf(w1, b0.x, w2 * c0.x));
            v[1] = fmaf(w0, a0.y, fmaf(w1, b0.y, w2 * c0.y));
            v[2] = fmaf(w0, a0.z, fmaf(w1, b0.z, w2 * c0.z));
            v[3] = fmaf(w0, a0.w, fmaf(w1, b0.w, w2 * c0.w));
        }
        uint32_t H, L; quant4(v, H, L);
        *(uint32_t*)(sm + p * A1_ST + c) = H;
        *(uint32_t*)(sm + A1L_OFF + p * A1_ST + c) = L;
    }

    // ---- GEMM1: 2 passes x 12 k32 chunks, int8 dual-plane ----
    int acc1[8][4], acc2[8][4];
#pragma unroll
    for (int nt = 0; nt < 8; nt++)
#pragma unroll
        for (int i = 0; i < 4; i++) { acc1[nt][i] = 0; acc2[nt][i] = 0; }

    const uint32_t a_base = sb + (uint32_t)((m0 + r8 + gm) * A1_ST) + gk * 2;

    auto epilogue1 = [&](int np) {
        const uint32_t hiB = sb + (np ? H1B_HI : H1A_HI);
#pragma unroll
        for (int nt = 0; nt < 8; nt++) {
            const int cloc = nw0 + nt * 8 + (lane & 3) * 2;
            const int o = np * 128 + cloc;
            const float s0 = __ldg(g_scale1 + o), s1 = __ldg(g_scale1 + o + 1);
            const float bb0 = __ldg(g_b1f + o), bb1 = __ldg(g_b1f + o + 1);
            const int row = m0 + (lane >> 2);
            float v0 = fmaxf(fmaf(fmaf((float)acc2[nt][0], 7.87401575e-3f, (float)acc1[nt][0]), s0, bb0), 0.f);
            float v1 = fmaxf(fmaf(fmaf((float)acc2[nt][1], 7.87401575e-3f, (float)acc1[nt][1]), s1, bb1), 0.f);
            float v2_ = fmaxf(fmaf(fmaf((float)acc2[nt][2], 7.87401575e-3f, (float)acc1[nt][2]), s0, bb0), 0.f);
            float v3 = fmaxf(fmaf(fmaf((float)acc2[nt][3], 7.87401575e-3f, (float)acc1[nt][3]), s1, bb1), 0.f);
            uint32_t hi, lo;
            split2(v0, v1, hi, lo);
            *(uint32_t*)(sm + (hiB - sb) + row * H1_ST + cloc * 2) = hi;
            *(uint32_t*)(sm + (hiB - sb) + H1_LO + row * H1_ST + cloc * 2) = lo;
            split2(v2_, v3, hi, lo);
            *(uint32_t*)(sm + (hiB - sb) + (row + 8) * H1_ST + cloc * 2) = hi;
            *(uint32_t*)(sm + (hiB - sb) + H1_LO + (row + 8) * H1_ST + cloc * 2) = lo;
        }
#pragma unroll
        for (int nt = 0; nt < 8; nt++)
#pragma unroll
            for (int i = 0; i < 4; i++) { acc1[nt][i] = 0; acc2[nt][i] = 0; }
    };

    for (int g = 0; g < 24; g++) {
        if (g == 12) epilogue1(0);   // pass0 results -> H1a (disjoint region, no barrier)

        const uint32_t Bu = sb + B1_OFF + (g & 1) * B1_BUF;
        CP_WAIT0();
        __syncthreads();             // B1(g) + (g==0: A stores) visible; prior buf consumed

        if (g + 1 < 24) {
            const unsigned char* srcH = g_W1qh + (size_t)(g + 1) * W1QC;
            const unsigned char* srcL = g_W1ql + (size_t)(g + 1) * W1QC;
            const uint32_t dH = sb + B1_OFF + ((g + 1) & 1) * B1_BUF;
            for (int i = tid * 16; i < B1_LO; i += NTHR * 16) {
                cpa16(dH + i, srcH + i);
                cpa16(dH + B1_LO + i, srcL + i);
            }
            CP_COMMIT();
        }

        const int kc = (g % 12) * 32;
        uint32_t ah[4], al[4];
        ldsm4(ah, a_base + kc);
        ldsm4(al, a_base + kc + A1L_OFF);

        uint32_t bh[16];
#pragma unroll
        for (int w4 = 0; w4 < 4; w4++)
            ldsm4(&bh[w4 * 4], Bu + (uint32_t)((nw0 + w4 * 16 + r8 + gk) * B1_ST) + gm * 2);
#pragma unroll
        for (int nt = 0; nt < 8; nt++) mma_s8(acc1[nt], ah, &bh[nt * 2]);
#pragma unroll
        for (int nt = 0; nt < 8; nt++) mma_s8(acc2[nt], al, &bh[nt * 2]);
        uint32_t bl[16];
#pragma unroll
        for (int w4 = 0; w4 < 4; w4++)
            ldsm4(&bl[w4 * 4], Bu + B1_LO + (uint32_t)((nw0 + w4 * 16 + r8 + gk) * B1_ST) + gm * 2);
#pragma unroll
        for (int nt = 0; nt < 8; nt++) mma_s8(acc2[nt], ah, &bl[nt * 2]);
    }

    __syncthreads();                 // all A/B1 reads done; regions reusable

    // prefetch W2 chunk 0 (B2 region overlays dead A-tail/B1)
    {
        const uint32_t dH = sb + B2_OFF;
        for (int i = tid * 16; i < W2CB; i += NTHR * 16) {
            cpa16(dH + i, g_W2h + i);
            cpa16(dH + B2_LO + i, g_W2l + i);
        }
        CP_COMMIT();
    }
    epilogue1(1);                    // pass1 results -> H1b (overlays dead A region)

    // ---- GEMM2: h1[64][256] x W2^T -> out[64][128], bf16 x3 ----
    float d2[8][4];
#pragma unroll
    for (int nt = 0; nt < 8; nt++)
#pragma unroll
        for (int i = 0; i < 4; i++) d2[nt][i] = 0.f;

    for (int cj = 0; cj < 8; cj++) {
        const uint32_t Bu = sb + B2_OFF + (cj & 1) * B2_BUF;
        CP_WAIT0();
        __syncthreads();             // B2(cj) + (cj==0: H1b stores) visible

        if (cj + 1 < 8) {
            const unsigned char* srcH = g_W2h + (size_t)(cj + 1) * W2CB;
            const unsigned char* srcL = g_W2l + (size_t)(cj + 1) * W2CB;
            const uint32_t dH = sb + B2_OFF + ((cj + 1) & 1) * B2_BUF;
            for (int i = tid * 16; i < W2CB; i += NTHR * 16) {
                cpa16(dH + i, srcH + i);
                cpa16(dH + B2_LO + i, srcL + i);
            }
            CP_COMMIT();
        }

        const int half = cj >> 2;
        const uint32_t hBase = sb + (half ? H1B_HI : H1A_HI);
        const int kk = cj * 32 - half * 128;

#pragma unroll
        for (int ks = 0; ks < 2; ks++) {
            uint32_t ah[4], al[4];
            const uint32_t aad = hBase + (uint32_t)((m0 + r8 + gm) * H1_ST
                                                    + (kk + ks * 16 + gk) * 2);
            ldsm4(ah, aad);
            ldsm4(al, aad + H1_LO);
            uint32_t bbf[8][2];
#pragma unroll
            for (int np4 = 0; np4 < 4; np4++)
                ldsm4(&bbf[2 * np4][0],
                      Bu + (uint32_t)((nw0 + np4 * 16 + r8 + gk) * CHS + (ks * 16 + gm) * 2));
#pragma unroll
            for (int nt = 0; nt < 8; nt++) mma_bf16(d2[nt], ah, bbf[nt]);
#pragma unroll
            for (int nt = 0; nt < 8; nt++) mma_bf16(d2[nt], al, bbf[nt]);
#pragma unroll
            for (int np4 = 0; np4 < 4; np4++)
                ldsm4(&bbf[2 * np4][0],
                      Bu + B2_LO + (uint32_t)((nw0 + np4 * 16 + r8 + gk) * CHS
                                              + (ks * 16 + gm) * 2));
#pragma unroll
            for (int nt = 0; nt < 8; nt++) mma_bf16(d2[nt], ah, bbf[nt]);
        }
    }

    // ---- epilogue2: bias + ReLU -> fp32 out ----
#pragma unroll
    for (int nt = 0; nt < 8; nt++) {
        const int col = nw0 + nt * 8 + (lane & 3) * 2;
        const float bb0 = __ldg(g_b2f + col), bb1 = __ldg(g_b2f + col + 1);
        const int row = m0 + (lane >> 2);
        float2 v0 = make_float2(fmaxf(d2[nt][0] + bb0, 0.f), fmaxf(d2[nt][1] + bb1, 0.f));
        float2 v1 = make_float2(fmaxf(d2[nt][2] + bb0, 0.f), fmaxf(d2[nt][3] + bb1, 0.f));
        *(float2*)(out + ((size_t)(b * NPTS + n0g + row)) * H2 + col) = v0;
        *(float2*)(out + ((size_t)(b * NPTS + n0g + row + 8)) * H2 + col) = v1;
    }
}

// ---------------- launch ----------------
extern "C" void kernel_launch(void* const* d_in, const int* in_sizes, int n_in,
                              void* d_out, int out_size) {
    const float* xyz1  = (const float*)d_in[0];
    const float* feat1 = (const float*)d_in[1];
    const float* xyz2  = (const float*)d_in[2];
    const float* feat2 = (const float*)d_in[3];
    const float* W1  = (const float*)d_in[4];
    const float* b1  = (const float*)d_in[5];
    const float* g1  = (const float*)d_in[6];
    const float* be1 = (const float*)d_in[7];
    const float* m1  = (const float*)d_in[8];
    const float* v1  = (const float*)d_in[9];
    const float* W2  = (const float*)d_in[10];
    const float* b2  = (const float*)d_in[11];
    const float* g2  = (const float*)d_in[12];
    const float* be2 = (const float*)d_in[13];
    const float* m2  = (const float*)d_in[14];
    const float* v2  = (const float*)d_in[15];
    float* out = (float*)d_out;

    cudaFuncSetAttribute(nn_kernel, cudaFuncAttributeMaxDynamicSharedMemorySize,
                         SPTS * (int)sizeof(float4));
    cudaFuncSetAttribute(fused_kernel, cudaFuncAttributeMaxDynamicSharedMemorySize,
                         SMEM_BYTES);

    prep_kernel<<<64, 256>>>(W1, b1, g1, be1, m1, v1, W2, b2, g2, be2, m2, v2);
    nn_kernel<<<dim3(NPTS / 256, BB), 256, SPTS * sizeof(float4)>>>(xyz1, xyz2);
    fused_kernel<<<dim3(NPTS / NPB, BB), NTHR, SMEM_BYTES>>>(feat1, feat2, out);
}

// round 10
// speedup vs baseline: 1.8991x; 1.8991x over previous
#include <cuda_runtime.h>
#include <cuda_bf16.h>
#include <cuda_fp16.h>
#include <cstdint>

// Problem constants
#define BB   4
#define NPTS 16384
#define SPTS 4096
#define C1   128
#define C2   256
#define CIN  384
#define H1   256
#define H2   128

#define NPB  64          // points per fused block
#define NTHR 256

// Tile row strides: k32 chunk rows = 32 elems*2B + 16 pad = 80B
// (5 16B-granules, coprime 8 -> conflict-free ldmatrix)
// H1 rows = 256 bf16 + 8 pad = 264 bf16 = 528B (33 granules, coprime 8)
#define CHS  80
#define H1SB 528

// Weight chunk sizes (one k32 chunk): W1 fp16 single plane: 256 rows x 80B = 20480
//                                     W2 bf16 hi/lo planes: 128 rows x 80B = 10240 each
#define W1CB 20480
#define W2CB 10240

__device__ __align__(16) unsigned char g_W1f[12 * W1CB];   // fp16, BN-folded
__device__ __align__(16) unsigned char g_W2h[8 * W2CB];
__device__ __align__(16) unsigned char g_W2l[8 * W2CB];
__device__ float g_b1f[H1];
__device__ float g_b2f[H2];
__device__ int   g_ni[BB * NPTS * 3];
__device__ float g_nw[BB * NPTS * 3];

// ---------------- helpers ----------------
__device__ __forceinline__ uint32_t smem_to_u32(const void* p) {
    uint32_t a;
    asm("{ .reg .u64 t; cvta.to.shared.u64 t, %1; cvt.u32.u64 %0, t; }" : "=r"(a) : "l"(p));
    return a;
}
__device__ __forceinline__ void ldsm4(uint32_t* r, uint32_t a) {
    asm volatile("ldmatrix.sync.aligned.m8n8.x4.shared.b16 {%0,%1,%2,%3}, [%4];"
                 : "=r"(r[0]), "=r"(r[1]), "=r"(r[2]), "=r"(r[3]) : "r"(a));
}
__device__ __forceinline__ void mma_bf16(float* d, const uint32_t* a, const uint32_t* b) {
    asm volatile("mma.sync.aligned.m16n8k16.row.col.f32.bf16.bf16.f32 "
                 "{%0,%1,%2,%3}, {%4,%5,%6,%7}, {%8,%9}, {%0,%1,%2,%3};"
                 : "+f"(d[0]), "+f"(d[1]), "+f"(d[2]), "+f"(d[3])
                 : "r"(a[0]), "r"(a[1]), "r"(a[2]), "r"(a[3]), "r"(b[0]), "r"(b[1]));
}
__device__ __forceinline__ void mma_f16(float* d, const uint32_t* a, const uint32_t* b) {
    asm volatile("mma.sync.aligned.m16n8k16.row.col.f32.f16.f16.f32 "
                 "{%0,%1,%2,%3}, {%4,%5,%6,%7}, {%8,%9}, {%0,%1,%2,%3};"
                 : "+f"(d[0]), "+f"(d[1]), "+f"(d[2]), "+f"(d[3])
                 : "r"(a[0]), "r"(a[1]), "r"(a[2]), "r"(a[3]), "r"(b[0]), "r"(b[1]));
}
__device__ __forceinline__ void cpa16(uint32_t dst, const void* src) {
    asm volatile("cp.async.cg.shared.global [%0], [%1], 16;" :: "r"(dst), "l"(src));
}
#define CP_COMMIT() asm volatile("cp.async.commit_group;" ::: "memory")
#define CP_WAIT0()  asm volatile("cp.async.wait_group 0;" ::: "memory")

// bf16 hi/lo split (GEMM2, exact path)
__device__ __forceinline__ void split2(float v0, float v1, uint32_t& hi, uint32_t& lo) {
    __nv_bfloat16 h0 = __float2bfloat16(v0), h1 = __float2bfloat16(v1);
    float l0 = v0 - __bfloat162float(h0), l1 = v1 - __bfloat162float(h1);
    hi = (uint32_t)__bfloat16_as_ushort(h0) | ((uint32_t)__bfloat16_as_ushort(h1) << 16);
    lo = (uint32_t)__bfloat16_as_ushort(__float2bfloat16(l0)) |
         ((uint32_t)__bfloat16_as_ushort(__float2bfloat16(l1)) << 16);
}
__device__ __forceinline__ void pack_split4(const float* v, uint2& H, uint2& L) {
    uint32_t h0, l0, h1, l1;
    split2(v[0], v[1], h0, l0);
    split2(v[2], v[3], h1, l1);
    H = make_uint2(h0, h1);
    L = make_uint2(l0, l1);
}
// fp16 hi/lo split (GEMM1 activations: exact to 2^-21)
__device__ __forceinline__ void split2h(float v0, float v1, uint32_t& hi, uint32_t& lo) {
    __half h0 = __float2half_rn(v0), h1 = __float2half_rn(v1);
    float l0 = v0 - __half2float(h0), l1 = v1 - __half2float(h1);
    hi = (uint32_t)__half_as_ushort(h0) | ((uint32_t)__half_as_ushort(h1) << 16);
    lo = (uint32_t)__half_as_ushort(__float2half_rn(l0)) |
         ((uint32_t)__half_as_ushort(__float2half_rn(l1)) << 16);
}
__device__ __forceinline__ void pack_split4h(const float* v, uint2& H, uint2& L) {
    uint32_t h0, l0, h1, l1;
    split2h(v[0], v[1], h0, l0);
    split2h(v[2], v[3], h1, l1);
    H = make_uint2(h0, h1);
    L = make_uint2(l0, l1);
}
__device__ __forceinline__ uint32_t packh2(float v0, float v1) {
    return (uint32_t)__half_as_ushort(__float2half_rn(v0)) |
           ((uint32_t)__half_as_ushort(__float2half_rn(v1)) << 16);
}

// ---------------- kernel A: fold BN, lay out weights (fully parallel) ----------------
__global__ void prep_kernel(const float* __restrict__ W1, const float* __restrict__ b1,
                            const float* __restrict__ g1, const float* __restrict__ be1,
                            const float* __restrict__ m1, const float* __restrict__ v1,
                            const float* __restrict__ W2, const float* __restrict__ b2,
                            const float* __restrict__ g2, const float* __restrict__ be2,
                            const float* __restrict__ m2, const float* __restrict__ v2) {
    int idx = blockIdx.x * blockDim.x + threadIdx.x;
    int stride = gridDim.x * blockDim.x;

    // W1 -> fp16 single plane, k32 chunks of [256 rows][80B]
    for (int g = idx; g < 256 * 96; g += stride) {
        int o = g / 96, k0 = (g % 96) * 4;
        float a = g1[o] * rsqrtf(v1[o] + 1e-5f);
        float v0 = W1[o * CIN + k0 + 0] * a;
        float v1_ = W1[o * CIN + k0 + 1] * a;
        float v2_ = W1[o * CIN + k0 + 2] * a;
        float v3 = W1[o * CIN + k0 + 3] * a;
        uint2 H = make_uint2(packh2(v0, v1_), packh2(v2_, v3));
        int chunk = k0 >> 5, kc = k0 & 31;
        *(uint2*)(g_W1f + (size_t)chunk * W1CB + o * CHS + kc * 2) = H;
    }
    // W2 -> bf16 hi/lo, k32 chunks
    for (int g = idx; g < 128 * 64; g += stride) {
        int o = g / 64, k0 = (g % 64) * 4;
        float a = g2[o] * rsqrtf(v2[o] + 1e-5f);
        float vv[4];
#pragma unroll
        for (int j = 0; j < 4; j++) vv[j] = W2[o * H1 + k0 + j] * a;
        uint2 H, L; pack_split4(vv, H, L);
        int chunk = k0 >> 5, kc = k0 & 31;
        size_t off = (size_t)chunk * W2CB + o * CHS + kc * 2;
        *(uint2*)(g_W2h + off) = H;
        *(uint2*)(g_W2l + off) = L;
    }
    for (int o = idx; o < H1; o += stride) {
        float a = g1[o] * rsqrtf(v1[o] + 1e-5f);
        g_b1f[o] = (b1[o] - m1[o]) * a + be1[o];
    }
    for (int o = idx; o < H2; o += stride) {
        float a = g2[o] * rsqrtf(v2[o] + 1e-5f);
        g_b2f[o] = (b2[o] - m2[o]) * a + be2[o];
    }
}

// ---------------- kernel B: exact 3-NN + interpolation weights (unchanged) ----------
__global__ void __launch_bounds__(256) nn_kernel(const float* __restrict__ xyz1,
                                                 const float* __restrict__ xyz2) {
    extern __shared__ float4 sc[];
    const int b = blockIdx.y;
    const int n = blockIdx.x * 256 + threadIdx.x;

    const float* x2 = xyz2 + b * SPTS * 3;
    for (int s = threadIdx.x; s < SPTS; s += 256) {
        float x = x2[s * 3 + 0], y = x2[s * 3 + 1], z = x2[s * 3 + 2];
        sc[s] = make_float4(fmaf(x, x, fmaf(y, y, z * z)), -2.f * x, -2.f * y, -2.f * z);
    }
    __syncthreads();

    const float* qq = xyz1 + (b * NPTS + n) * 3;
    const float qx = qq[0], qy = qq[1], qz = qq[2];

    const float INF = __int_as_float(0x7f800000);
    float d0 = INF, d1 = INF, d2 = INF;
    int i0 = 0, i1 = 0, i2 = 0;

#pragma unroll 4
    for (int s = 0; s < SPTS; s++) {
        float4 c = sc[s];
        float t = fmaf(c.y, qx, c.x);
        t = fmaf(c.z, qy, t);
        t = fmaf(c.w, qz, t);
        if (t < d2) {
            if (t < d1) {
                d2 = d1; i2 = i1;
                if (t < d0) { d1 = d0; i1 = i0; d0 = t; i0 = s; }
                else        { d1 = t;  i1 = s; }
            } else { d2 = t; i2 = s; }
        }
    }

    const float qn = fmaf(qx, qx, fmaf(qy, qy, qz * qz));
    float r0 = 1.f / ((d0 + qn) + 1e-8f);
    float r1 = 1.f / ((d1 + qn) + 1e-8f);
    float r2 = 1.f / ((d2 + qn) + 1e-8f);
    float inv = 1.f / (r0 + r1 + r2);

    const int base = (b * NPTS + n) * 3;
    g_ni[base + 0] = i0; g_ni[base + 1] = i1; g_ni[base + 2] = i2;
    g_nw[base + 0] = r0 * inv; g_nw[base + 1] = r1 * inv; g_nw[base + 2] = r2 * inv;
}

// ---------------- kernel C: fp16x2 GEMM1 + bf16x3 GEMM2, 2 blocks/SM ----------------
// 64 points/block, 256 threads (8 warps).
// SMEM (bytes):
//  phase1: A1 bufs 2 x (hi 5120 | lo 5120) @0          .. 20480
//          B1 bufs 2 x 20480 (fp16 single plane) @20480 .. 61440
//  phase2: H1 hi @0 (33792) | lo @33792 (33792)        .. 67584
//          B2 bufs 2 x (hi 10240 | lo 10240) @67584    .. 108544
#define A1_OFF  0
#define A1_BUF  10240
#define A1_LO   5120
#define B1_OFF  20480
#define B1_BUF  20480
#define H1H_OFF 0
#define H1L_OFF 33792
#define B2_OFF  67584
#define B2_BUF  20480
#define B2_LO   10240
#define SMEM_BYTES 108544

__global__ void __launch_bounds__(NTHR, 2) fused_kernel(const float* __restrict__ feat1,
                                                        const float* __restrict__ feat2,
                                                        float* __restrict__ out) {
    extern __shared__ __align__(128) char sm[];
    const uint32_t sb = smem_to_u32(sm);
    const int tid  = threadIdx.x;
    const int lane = tid & 31;
    const int wid  = tid >> 5;
    const int b    = blockIdx.y;
    const int n0g  = blockIdx.x * NPB;

    // producer mapping: 4 threads per point
    const int p = tid >> 2;
    const int q = tid & 3;
    const int nbase = (b * NPTS + n0g + p) * 3;
    const int j0 = g_ni[nbase], j1 = g_ni[nbase + 1], j2 = g_ni[nbase + 2];
    const float w0 = g_nw[nbase], w1 = g_nw[nbase + 1], w2 = g_nw[nbase + 2];

    // ldmatrix decomposition
    const int r8 = lane & 7;
    const int g4 = lane >> 3;
    const int gm = (g4 & 1) << 3;
    const int gk = (g4 >> 1) << 3;

    // warp tiles: GEMM1 M16xN128, GEMM2 M16xN64
    const int m0  = (wid >> 1) * 16;
    const int nh0 = (wid & 1) * 128;
    const int n20 = (wid & 1) * 64;

    float d1[16][4];
#pragma unroll
    for (int nt = 0; nt < 16; nt++)
#pragma unroll
        for (int i = 0; i < 4; i++) d1[nt][i] = 0.f;

    float4 pf0, pf1, pf2;

    auto ldg_part = [&](int nc, int h) {
        const int cl = q * 8 + h * 4;
        if (nc < 4) {
            pf0 = __ldg((const float4*)(feat1 + ((size_t)(b * NPTS + n0g + p)) * C1
                                        + nc * 32 + cl));
        } else {
            const int c2 = (nc - 4) * 32 + cl;
            pf0 = __ldg((const float4*)(feat2 + ((size_t)b * SPTS + j0) * C2 + c2));
            pf1 = __ldg((const float4*)(feat2 + ((size_t)b * SPTS + j1) * C2 + c2));
            pf2 = __ldg((const float4*)(feat2 + ((size_t)b * SPTS + j2) * C2 + c2));
        }
    };
    auto sts_part = [&](int nc, int h) {
        float v[4];
        if (nc < 4) {
            v[0] = pf0.x; v[1] = pf0.y; v[2] = pf0.z; v[3] = pf0.w;
        } else {
            v[0] = fmaf(w0, pf0.x, fmaf(w1, pf1.x, w2 * pf2.x));
            v[1] = fmaf(w0, pf0.y, fmaf(w1, pf1.y, w2 * pf2.y));
            v[2] = fmaf(w0, pf0.z, fmaf(w1, pf1.z, w2 * pf2.z));
            v[3] = fmaf(w0, pf0.w, fmaf(w1, pf1.w, w2 * pf2.w));
        }
        uint2 H, L; pack_split4h(v, H, L);
        char* dst = sm + A1_OFF + (nc & 1) * A1_BUF + p * CHS + (q * 8 + h * 4) * 2;
        *(uint2*)dst = H;
        *(uint2*)(dst + A1_LO) = L;
    };
    auto consume1 = [&](uint32_t Au, uint32_t Bu, int ks) {
        uint32_t ah[4], al[4];
        const uint32_t aad = Au + (uint32_t)((m0 + r8 + gm) * CHS + (ks * 16 + gk) * 2);
        ldsm4(ah, aad);
        ldsm4(al, aad + A1_LO);
#pragma unroll
        for (int nb = 0; nb < 2; nb++) {
            uint32_t bbf[8][2];
#pragma unroll
            for (int np = 0; np < 4; np++)
                ldsm4(&bbf[2 * np][0],
                      Bu + (uint32_t)((nh0 + nb * 64 + np * 16 + r8 + gk) * CHS
                                      + (ks * 16 + gm) * 2));
#pragma unroll
            for (int nt = 0; nt < 8; nt++) mma_f16(d1[nb * 8 + nt], ah, bbf[nt]);
#pragma unroll
            for (int nt = 0; nt < 8; nt++) mma_f16(d1[nb * 8 + nt], al, bbf[nt]);
        }
    };

    // ---- pre-loop: produce chunk 0 + cp.async W1 chunk 0 ----
    ldg_part(0, 0); sts_part(0, 0);
    ldg_part(0, 1); sts_part(0, 1);
    {
        const uint32_t dH = sb + B1_OFF;
        for (int i = tid * 16; i < W1CB; i += NTHR * 16)
            cpa16(dH + i, g_W1f + i);
        CP_COMMIT();
    }

    // ---- phase 1: 12 chunks of k32, fp16 2-product ----
    for (int ci = 0; ci < 12; ci++) {
        const int s = ci & 1;
        const uint32_t Au = sb + A1_OFF + s * A1_BUF;
        const uint32_t Bu = sb + B1_OFF + s * B1_BUF;
        const int nc = ci + 1;

        CP_WAIT0();          // W1(ci) arrived (thread-local)
        __syncthreads();     // W1(ci)/A(ci) visible to all; consume(ci-1) done everywhere

        if (nc < 12) {       // prefetch weights for next chunk during this mma phase
            const unsigned char* srcW = g_W1f + (size_t)nc * W1CB;
            const uint32_t dH = sb + B1_OFF + (nc & 1) * B1_BUF;
            for (int i = tid * 16; i < W1CB; i += NTHR * 16)
                cpa16(dH + i, srcW + i);
            CP_COMMIT();
        }

        if (nc < 12) ldg_part(nc, 0);
        consume1(Au, Bu, 0);
        if (nc < 12) { sts_part(nc, 0); ldg_part(nc, 1); }
        consume1(Au, Bu, 1);
        if (nc < 12) sts_part(nc, 1);
    }
    __syncthreads();         // all consumes done before H1/B2 region overwrite

    // ---- prefetch W2 chunk 0, then epilogue1 (covers the cp.async) ----
    {
        const uint32_t dH = sb + B2_OFF;
        for (int i = tid * 16; i < W2CB; i += NTHR * 16) {
            cpa16(dH + i, g_W2h + i);
            cpa16(dH + B2_LO + i, g_W2l + i);
        }
        CP_COMMIT();
    }
    // epilogue1: bias + ReLU + bf16 split -> H1 smem
#pragma unroll
    for (int nt = 0; nt < 16; nt++) {
        const int col = nh0 + nt * 8 + (lane & 3) * 2;
        const float bb0 = __ldg(g_b1f + col), bb1 = __ldg(g_b1f + col + 1);
        const int row = m0 + (lane >> 2);
        uint32_t hi, lo;
        split2(fmaxf(d1[nt][0] + bb0, 0.f), fmaxf(d1[nt][1] + bb1, 0.f), hi, lo);
        *(uint32_t*)(sm + H1H_OFF + row * H1SB + col * 2) = hi;
        *(uint32_t*)(sm + H1L_OFF + row * H1SB + col * 2) = lo;
        split2(fmaxf(d1[nt][2] + bb0, 0.f), fmaxf(d1[nt][3] + bb1, 0.f), hi, lo);
        *(uint32_t*)(sm + H1H_OFF + (row + 8) * H1SB + col * 2) = hi;
        *(uint32_t*)(sm + H1L_OFF + (row + 8) * H1SB + col * 2) = lo;
    }

    // ---- phase 2: GEMM2, 8 chunks of k32, bf16 3-product ----
    float d2[8][4];
#pragma unroll
    for (int nt = 0; nt < 8; nt++)
#pragma unroll
        for (int i = 0; i < 4; i++) d2[nt][i] = 0.f;

    for (int cj = 0; cj < 8; cj++) {
        const int s = cj & 1;
        const uint32_t Bu = sb + B2_OFF + s * B2_BUF;
        const int ncj = cj + 1;

        CP_WAIT0();          // W2(cj) arrived
        __syncthreads();     // also orders H1 writes (cj==0) and buffer reuse

        if (ncj < 8) {
            const unsigned char* srcH = g_W2h + (size_t)ncj * W2CB;
            const unsigned char* srcL = g_W2l + (size_t)ncj * W2CB;
            const uint32_t dH = sb + B2_OFF + (ncj & 1) * B2_BUF;
            for (int i = tid * 16; i < W2CB; i += NTHR * 16) {
                cpa16(dH + i, srcH + i);
                cpa16(dH + B2_LO + i, srcL + i);
            }
            CP_COMMIT();
        }

#pragma unroll
        for (int ks = 0; ks < 2; ks++) {
            uint32_t ah[4], al[4];
            const uint32_t aad = sb + (uint32_t)((m0 + r8 + gm) * H1SB
                                                 + (cj * 32 + ks * 16 + gk) * 2);
            ldsm4(ah, aad + H1H_OFF);
            ldsm4(al, aad + H1L_OFF);
            uint32_t bbf[8][2];
#pragma unroll
            for (int np = 0; np < 4; np++)
                ldsm4(&bbf[2 * np][0],
                      Bu + (uint32_t)((n20 + np * 16 + r8 + gk) * CHS + (ks * 16 + gm) * 2));
#pragma unroll
            for (int nt = 0; nt < 8; nt++) mma_bf16(d2[nt], ah, bbf[nt]);
#pragma unroll
            for (int nt = 0; nt < 8; nt++) mma_bf16(d2[nt], al, bbf[nt]);
#pragma unroll
            for (int np = 0; np < 4; np++)
                ldsm4(&bbf[2 * np][0],
                      Bu + B2_LO + (uint32_t)((n20 + np * 16 + r8 + gk) * CHS
                                              + (ks * 16 + gm) * 2));
#pragma unroll
            for (int nt = 0; nt < 8; nt++) mma_bf16(d2[nt], ah, bbf[nt]);
        }
    }

    // ---- epilogue2: bias + ReLU -> fp32 out ----
#pragma unroll
    for (int nt = 0; nt < 8; nt++) {
        const int col = n20 + nt * 8 + (lane & 3) * 2;
        const float bb0 = __ldg(g_b2f + col), bb1 = __ldg(g_b2f + col + 1);
        const int row = m0 + (lane >> 2);
        float2 v0 = make_float2(fmaxf(d2[nt][0] + bb0, 0.f), fmaxf(d2[nt][1] + bb1, 0.f));
        float2 v1 = make_float2(fmaxf(d2[nt][2] + bb0, 0.f), fmaxf(d2[nt][3] + bb1, 0.f));
        *(float2*)(out + ((size_t)(b * NPTS + n0g + row)) * H2 + col) = v0;
        *(float2*)(out + ((size_t)(b * NPTS + n0g + row + 8)) * H2 + col) = v1;
    }
}

// ---------------- launch ----------------
extern "C" void kernel_launch(void* const* d_in, const int* in_sizes, int n_in,
                              void* d_out, int out_size) {
    const float* xyz1  = (const float*)d_in[0];
    const float* feat1 = (const float*)d_in[1];
    const float* xyz2  = (const float*)d_in[2];
    const float* feat2 = (const float*)d_in[3];
    const float* W1  = (const float*)d_in[4];
    const float* b1  = (const float*)d_in[5];
    const float* g1  = (const float*)d_in[6];
    const float* be1 = (const float*)d_in[7];
    const float* m1  = (const float*)d_in[8];
    const float* v1  = (const float*)d_in[9];
    const float* W2  = (const float*)d_in[10];
    const float* b2  = (const float*)d_in[11];
    const float* g2  = (const float*)d_in[12];
    const float* be2 = (const float*)d_in[13];
    const float* m2  = (const float*)d_in[14];
    const float* v2  = (const float*)d_in[15];
    float* out = (float*)d_out;

    cudaFuncSetAttribute(nn_kernel, cudaFuncAttributeMaxDynamicSharedMemorySize,
                         SPTS * (int)sizeof(float4));
    cudaFuncSetAttribute(fused_kernel, cudaFuncAttributeMaxDynamicSharedMemorySize,
                         SMEM_BYTES);

    prep_kernel<<<64, 256>>>(W1, b1, g1, be1, m1, v1, W2, b2, g2, be2, m2, v2);
    nn_kernel<<<dim3(NPTS / 256, BB), 256, SPTS * sizeof(float4)>>>(xyz1, xyz2);
    fused_kernel<<<dim3(NPTS / NPB, BB), NTHR, SMEM_BYTES>>>(feat1, feat2, out);
}

// round 11
// speedup vs baseline: 2.1271x; 1.1200x over previous
#include <cuda_runtime.h>
#include <cuda_bf16.h>
#include <cuda_fp16.h>
#include <cstdint>

// Problem constants
#define BB   4
#define NPTS 16384
#define SPTS 4096
#define C1   128
#define C2   256
#define CIN  384
#define H1   256
#define H2   128

#define NPB  64          // points per fused block
#define NTHR 256

// Tile row strides: k32 chunk rows = 32 elems*2B + 16 pad = 80B
// (5 16B-granules, coprime 8 -> conflict-free ldmatrix)
// H1 rows = 256 fp16 + 8 pad = 264 elems = 528B (33 granules, coprime 8)
#define CHS  80
#define H1SB 528

// Weight chunk sizes (one k32 chunk, fp16 single plane):
//   W1: 256 rows x 80B = 20480 ; W2: 128 rows x 80B = 10240
#define W1CB 20480
#define W2CB 10240

__device__ __align__(16) unsigned char g_W1f[12 * W1CB];   // fp16, BN-folded
__device__ __align__(16) unsigned char g_W2f[8 * W2CB];    // fp16, BN-folded
__device__ float g_b1f[H1];
__device__ float g_b2f[H2];
__device__ int   g_ni[BB * NPTS * 3];
__device__ float g_nw[BB * NPTS * 3];

// ---------------- helpers ----------------
__device__ __forceinline__ uint32_t smem_to_u32(const void* p) {
    uint32_t a;
    asm("{ .reg .u64 t; cvta.to.shared.u64 t, %1; cvt.u32.u64 %0, t; }" : "=r"(a) : "l"(p));
    return a;
}
__device__ __forceinline__ void ldsm4(uint32_t* r, uint32_t a) {
    asm volatile("ldmatrix.sync.aligned.m8n8.x4.shared.b16 {%0,%1,%2,%3}, [%4];"
                 : "=r"(r[0]), "=r"(r[1]), "=r"(r[2]), "=r"(r[3]) : "r"(a));
}
__device__ __forceinline__ void mma_f16(float* d, const uint32_t* a, const uint32_t* b) {
    asm volatile("mma.sync.aligned.m16n8k16.row.col.f32.f16.f16.f32 "
                 "{%0,%1,%2,%3}, {%4,%5,%6,%7}, {%8,%9}, {%0,%1,%2,%3};"
                 : "+f"(d[0]), "+f"(d[1]), "+f"(d[2]), "+f"(d[3])
                 : "r"(a[0]), "r"(a[1]), "r"(a[2]), "r"(a[3]), "r"(b[0]), "r"(b[1]));
}
__device__ __forceinline__ void cpa16(uint32_t dst, const void* src) {
    asm volatile("cp.async.cg.shared.global [%0], [%1], 16;" :: "r"(dst), "l"(src));
}
#define CP_COMMIT() asm volatile("cp.async.commit_group;" ::: "memory")
#define CP_WAIT0()  asm volatile("cp.async.wait_group 0;" ::: "memory")

__device__ __forceinline__ uint32_t packh2(float v0, float v1) {
    return (uint32_t)__half_as_ushort(__float2half_rn(v0)) |
           ((uint32_t)__half_as_ushort(__float2half_rn(v1)) << 16);
}
// fp16 hi/lo split (h1 staging: exact to 2^-21)
__device__ __forceinline__ void split2h(float v0, float v1, uint32_t& hi, uint32_t& lo) {
    __half h0 = __float2half_rn(v0), h1 = __float2half_rn(v1);
    float l0 = v0 - __half2float(h0), l1 = v1 - __half2float(h1);
    hi = (uint32_t)__half_as_ushort(h0) | ((uint32_t)__half_as_ushort(h1) << 16);
    lo = (uint32_t)__half_as_ushort(__float2half_rn(l0)) |
         ((uint32_t)__half_as_ushort(__float2half_rn(l1)) << 16);
}

// ---------------- kernel A: fold BN, lay out fp16 weights (fully parallel) ----------
__global__ void prep_kernel(const float* __restrict__ W1, const float* __restrict__ b1,
                            const float* __restrict__ g1, const float* __restrict__ be1,
                            const float* __restrict__ m1, const float* __restrict__ v1,
                            const float* __restrict__ W2, const float* __restrict__ b2,
                            const float* __restrict__ g2, const float* __restrict__ be2,
                            const float* __restrict__ m2, const float* __restrict__ v2) {
    int idx = blockIdx.x * blockDim.x + threadIdx.x;
    int stride = gridDim.x * blockDim.x;

    // W1 -> fp16 single plane, k32 chunks of [256 rows][80B]
    for (int g = idx; g < 256 * 96; g += stride) {
        int o = g / 96, k0 = (g % 96) * 4;
        float a = g1[o] * rsqrtf(v1[o] + 1e-5f);
        float v0 = W1[o * CIN + k0 + 0] * a;
        float v1_ = W1[o * CIN + k0 + 1] * a;
        float v2_ = W1[o * CIN + k0 + 2] * a;
        float v3 = W1[o * CIN + k0 + 3] * a;
        uint2 H = make_uint2(packh2(v0, v1_), packh2(v2_, v3));
        int chunk = k0 >> 5, kc = k0 & 31;
        *(uint2*)(g_W1f + (size_t)chunk * W1CB + o * CHS + kc * 2) = H;
    }
    // W2 -> fp16 single plane, k32 chunks of [128 rows][80B]
    for (int g = idx; g < 128 * 64; g += stride) {
        int o = g / 64, k0 = (g % 64) * 4;
        float a = g2[o] * rsqrtf(v2[o] + 1e-5f);
        float v0 = W2[o * H1 + k0 + 0] * a;
        float v1_ = W2[o * H1 + k0 + 1] * a;
        float v2_ = W2[o * H1 + k0 + 2] * a;
        float v3 = W2[o * H1 + k0 + 3] * a;
        uint2 H = make_uint2(packh2(v0, v1_), packh2(v2_, v3));
        int chunk = k0 >> 5, kc = k0 & 31;
        *(uint2*)(g_W2f + (size_t)chunk * W2CB + o * CHS + kc * 2) = H;
    }
    for (int o = idx; o < H1; o += stride) {
        float a = g1[o] * rsqrtf(v1[o] + 1e-5f);
        g_b1f[o] = (b1[o] - m1[o]) * a + be1[o];
    }
    for (int o = idx; o < H2; o += stride) {
        float a = g2[o] * rsqrtf(v2[o] + 1e-5f);
        g_b2f[o] = (b2[o] - m2[o]) * a + be2[o];
    }
}

// ---------------- kernel B: exact 3-NN + interpolation weights (unchanged) ----------
__global__ void __launch_bounds__(256) nn_kernel(const float* __restrict__ xyz1,
                                                 const float* __restrict__ xyz2) {
    extern __shared__ float4 sc[];
    const int b = blockIdx.y;
    const int n = blockIdx.x * 256 + threadIdx.x;

    const float* x2 = xyz2 + b * SPTS * 3;
    for (int s = threadIdx.x; s < SPTS; s += 256) {
        float x = x2[s * 3 + 0], y = x2[s * 3 + 1], z = x2[s * 3 + 2];
        sc[s] = make_float4(fmaf(x, x, fmaf(y, y, z * z)), -2.f * x, -2.f * y, -2.f * z);
    }
    __syncthreads();

    const float* qq = xyz1 + (b * NPTS + n) * 3;
    const float qx = qq[0], qy = qq[1], qz = qq[2];

    const float INF = __int_as_float(0x7f800000);
    float d0 = INF, d1 = INF, d2 = INF;
    int i0 = 0, i1 = 0, i2 = 0;

#pragma unroll 4
    for (int s = 0; s < SPTS; s++) {
        float4 c = sc[s];
        float t = fmaf(c.y, qx, c.x);
        t = fmaf(c.z, qy, t);
        t = fmaf(c.w, qz, t);
        if (t < d2) {
            if (t < d1) {
                d2 = d1; i2 = i1;
                if (t < d0) { d1 = d0; i1 = i0; d0 = t; i0 = s; }
                else        { d1 = t;  i1 = s; }
            } else { d2 = t; i2 = s; }
        }
    }

    const float qn = fmaf(qx, qx, fmaf(qy, qy, qz * qz));
    float r0 = 1.f / ((d0 + qn) + 1e-8f);
    float r1 = 1.f / ((d1 + qn) + 1e-8f);
    float r2 = 1.f / ((d2 + qn) + 1e-8f);
    float inv = 1.f / (r0 + r1 + r2);

    const int base = (b * NPTS + n) * 3;
    g_ni[base + 0] = i0; g_ni[base + 1] = i1; g_ni[base + 2] = i2;
    g_nw[base + 0] = r0 * inv; g_nw[base + 1] = r1 * inv; g_nw[base + 2] = r2 * inv;
}

// ---------------- kernel C: fp16x1 GEMM1 + fp16x2 GEMM2, 2 blocks/SM ----------------
// 64 points/block, 256 threads (8 warps).
// SMEM (bytes):
//  phase1: A1 bufs 2 x 5120 (fp16 single) @0            .. 10240
//          B1 bufs 2 x 20480 (fp16 single) @10240       .. 51200
//  phase2: H1 hi @0 (33792) | lo @33792 (33792)         .. 67584
//          B2 bufs 2 x 10240 (fp16 single) @67584       .. 88064
#define A1_OFF  0
#define A1_BUF  5120
#define B1_OFF  10240
#define B1_BUF  20480
#define H1H_OFF 0
#define H1L_OFF 33792
#define B2_OFF  67584
#define B2_BUF  10240
#define SMEM_BYTES 88064

__global__ void __launch_bounds__(NTHR, 2) fused_kernel(const float* __restrict__ feat1,
                                                        const float* __restrict__ feat2,
                                                        float* __restrict__ out) {
    extern __shared__ __align__(128) char sm[];
    const uint32_t sb = smem_to_u32(sm);
    const int tid  = threadIdx.x;
    const int lane = tid & 31;
    const int wid  = tid >> 5;
    const int b    = blockIdx.y;
    const int n0g  = blockIdx.x * NPB;

    // producer mapping: 4 threads per point
    const int p = tid >> 2;
    const int q = tid & 3;
    const int nbase = (b * NPTS + n0g + p) * 3;
    const int j0 = g_ni[nbase], j1 = g_ni[nbase + 1], j2 = g_ni[nbase + 2];
    const float w0 = g_nw[nbase], w1 = g_nw[nbase + 1], w2 = g_nw[nbase + 2];

    // ldmatrix decomposition
    const int r8 = lane & 7;
    const int g4 = lane >> 3;
    const int gm = (g4 & 1) << 3;
    const int gk = (g4 >> 1) << 3;

    // warp tiles: GEMM1 M16xN128, GEMM2 M16xN64
    const int m0  = (wid >> 1) * 16;
    const int nh0 = (wid & 1) * 128;
    const int n20 = (wid & 1) * 64;

    float d1[16][4];
#pragma unroll
    for (int nt = 0; nt < 16; nt++)
#pragma unroll
        for (int i = 0; i < 4; i++) d1[nt][i] = 0.f;

    float4 pf0, pf1, pf2;

    auto ldg_part = [&](int nc, int h) {
        const int cl = q * 8 + h * 4;
        if (nc < 4) {
            pf0 = __ldg((const float4*)(feat1 + ((size_t)(b * NPTS + n0g + p)) * C1
                                        + nc * 32 + cl));
        } else {
            const int c2 = (nc - 4) * 32 + cl;
            pf0 = __ldg((const float4*)(feat2 + ((size_t)b * SPTS + j0) * C2 + c2));
            pf1 = __ldg((const float4*)(feat2 + ((size_t)b * SPTS + j1) * C2 + c2));
            pf2 = __ldg((const float4*)(feat2 + ((size_t)b * SPTS + j2) * C2 + c2));
        }
    };
    auto sts_part = [&](int nc, int h) {
        float v[4];
        if (nc < 4) {
            v[0] = pf0.x; v[1] = pf0.y; v[2] = pf0.z; v[3] = pf0.w;
        } else {
            v[0] = fmaf(w0, pf0.x, fmaf(w1, pf1.x, w2 * pf2.x));
            v[1] = fmaf(w0, pf0.y, fmaf(w1, pf1.y, w2 * pf2.y));
            v[2] = fmaf(w0, pf0.z, fmaf(w1, pf1.z, w2 * pf2.z));
            v[3] = fmaf(w0, pf0.w, fmaf(w1, pf1.w, w2 * pf2.w));
        }
        uint2 H = make_uint2(packh2(v[0], v[1]), packh2(v[2], v[3]));
        char* dst = sm + A1_OFF + (nc & 1) * A1_BUF + p * CHS + (q * 8 + h * 4) * 2;
        *(uint2*)dst = H;
    };
    auto consume1 = [&](uint32_t Au, uint32_t Bu, int ks) {
        uint32_t ah[4];
        const uint32_t aad = Au + (uint32_t)((m0 + r8 + gm) * CHS + (ks * 16 + gk) * 2);
        ldsm4(ah, aad);
#pragma unroll
        for (int nb = 0; nb < 2; nb++) {
            uint32_t bbf[8][2];
#pragma unroll
            for (int np = 0; np < 4; np++)
                ldsm4(&bbf[2 * np][0],
                      Bu + (uint32_t)((nh0 + nb * 64 + np * 16 + r8 + gk) * CHS
                                      + (ks * 16 + gm) * 2));
#pragma unroll
            for (int nt = 0; nt < 8; nt++) mma_f16(d1[nb * 8 + nt], ah, bbf[nt]);
        }
    };

    // ---- pre-loop: produce chunk 0 + cp.async W1 chunk 0 ----
    ldg_part(0, 0); sts_part(0, 0);
    ldg_part(0, 1); sts_part(0, 1);
    {
        const uint32_t dH = sb + B1_OFF;
        for (int i = tid * 16; i < W1CB; i += NTHR * 16)
            cpa16(dH + i, g_W1f + i);
        CP_COMMIT();
    }

    // ---- phase 1: 12 chunks of k32, fp16 single product ----
    for (int ci = 0; ci < 12; ci++) {
        const int s = ci & 1;
        const uint32_t Au = sb + A1_OFF + s * A1_BUF;
        const uint32_t Bu = sb + B1_OFF + s * B1_BUF;
        const int nc = ci + 1;

        CP_WAIT0();          // W1(ci) arrived (thread-local)
        __syncthreads();     // W1(ci)/A(ci) visible to all; consume(ci-1) done everywhere

        if (nc < 12) {       // prefetch weights for next chunk during this mma phase
            const unsigned char* srcW = g_W1f + (size_t)nc * W1CB;
            const uint32_t dH = sb + B1_OFF + (nc & 1) * B1_BUF;
            for (int i = tid * 16; i < W1CB; i += NTHR * 16)
                cpa16(dH + i, srcW + i);
            CP_COMMIT();
        }

        if (nc < 12) ldg_part(nc, 0);
        consume1(Au, Bu, 0);
        if (nc < 12) { sts_part(nc, 0); ldg_part(nc, 1); }
        consume1(Au, Bu, 1);
        if (nc < 12) sts_part(nc, 1);
    }
    __syncthreads();         // all consumes done before H1/B2 region overwrite

    // ---- prefetch W2 chunk 0, then epilogue1 (covers the cp.async) ----
    {
        const uint32_t dH = sb + B2_OFF;
        for (int i = tid * 16; i < W2CB; i += NTHR * 16)
            cpa16(dH + i, g_W2f + i);
        CP_COMMIT();
    }
    // epilogue1: bias + ReLU + fp16 hi/lo split -> H1 smem (split exact to 2^-21)
#pragma unroll
    for (int nt = 0; nt < 16; nt++) {
        const int col = nh0 + nt * 8 + (lane & 3) * 2;
        const float bb0 = __ldg(g_b1f + col), bb1 = __ldg(g_b1f + col + 1);
        const int row = m0 + (lane >> 2);
        uint32_t hi, lo;
        split2h(fmaxf(d1[nt][0] + bb0, 0.f), fmaxf(d1[nt][1] + bb1, 0.f), hi, lo);
        *(uint32_t*)(sm + H1H_OFF + row * H1SB + col * 2) = hi;
        *(uint32_t*)(sm + H1L_OFF + row * H1SB + col * 2) = lo;
        split2h(fmaxf(d1[nt][2] + bb0, 0.f), fmaxf(d1[nt][3] + bb1, 0.f), hi, lo);
        *(uint32_t*)(sm + H1H_OFF + (row + 8) * H1SB + col * 2) = hi;
        *(uint32_t*)(sm + H1L_OFF + (row + 8) * H1SB + col * 2) = lo;
    }

    // ---- phase 2: GEMM2, 8 chunks of k32, fp16 2-product (h1 exact, W2 rounded) ----
    float d2[8][4];
#pragma unroll
    for (int nt = 0; nt < 8; nt++)
#pragma unroll
        for (int i = 0; i < 4; i++) d2[nt][i] = 0.f;

    for (int cj = 0; cj < 8; cj++) {
        const int s = cj & 1;
        const uint32_t Bu = sb + B2_OFF + s * B2_BUF;
        const int ncj = cj + 1;

        CP_WAIT0();          // W2(cj) arrived
        __syncthreads();     // also orders H1 writes (cj==0) and buffer reuse

        if (ncj < 8) {
            const unsigned char* srcW = g_W2f + (size_t)ncj * W2CB;
            const uint32_t dH = sb + B2_OFF + (ncj & 1) * B2_BUF;
            for (int i = tid * 16; i < W2CB; i += NTHR * 16)
                cpa16(dH + i, srcW + i);
            CP_COMMIT();
        }

#pragma unroll
        for (int ks = 0; ks < 2; ks++) {
            uint32_t ah[4], al[4];
            const uint32_t aad = sb + (uint32_t)((m0 + r8 + gm) * H1SB
                                                 + (cj * 32 + ks * 16 + gk) * 2);
            ldsm4(ah, aad + H1H_OFF);
            ldsm4(al, aad + H1L_OFF);
            uint32_t bbf[8][2];
#pragma unroll
            for (int np = 0; np < 4; np++)
                ldsm4(&bbf[2 * np][0],
                      Bu + (uint32_t)((n20 + np * 16 + r8 + gk) * CHS + (ks * 16 + gm) * 2));
#pragma unroll
            for (int nt = 0; nt < 8; nt++) mma_f16(d2[nt], ah, bbf[nt]);
#pragma unroll
            for (int nt = 0; nt < 8; nt++) mma_f16(d2[nt], al, bbf[nt]);
        }
    }

    // ---- epilogue2: bias + ReLU -> fp32 out ----
#pragma unroll
    for (int nt = 0; nt < 8; nt++) {
        const int col = n20 + nt * 8 + (lane & 3) * 2;
        const float bb0 = __ldg(g_b2f + col), bb1 = __ldg(g_b2f + col + 1);
        const int row = m0 + (lane >> 2);
        float2 v0 = make_float2(fmaxf(d2[nt][0] + bb0, 0.f), fmaxf(d2[nt][1] + bb1, 0.f));
        float2 v1 = make_float2(fmaxf(d2[nt][2] + bb0, 0.f), fmaxf(d2[nt][3] + bb1, 0.f));
        *(float2*)(out + ((size_t)(b * NPTS + n0g + row)) * H2 + col) = v0;
        *(float2*)(out + ((size_t)(b * NPTS + n0g + row + 8)) * H2 + col) = v1;
    }
}

// ---------------- launch ----------------
extern "C" void kernel_launch(void* const* d_in, const int* in_sizes, int n_in,
                              void* d_out, int out_size) {
    const float* xyz1  = (const float*)d_in[0];
    const float* feat1 = (const float*)d_in[1];
    const float* xyz2  = (const float*)d_in[2];
    const float* feat2 = (const float*)d_in[3];
    const float* W1  = (const float*)d_in[4];
    const float* b1  = (const float*)d_in[5];
    const float* g1  = (const float*)d_in[6];
    const float* be1 = (const float*)d_in[7];
    const float* m1  = (const float*)d_in[8];
    const float* v1  = (const float*)d_in[9];
    const float* W2  = (const float*)d_in[10];
    const float* b2  = (const float*)d_in[11];
    const float* g2  = (const float*)d_in[12];
    const float* be2 = (const float*)d_in[13];
    const float* m2  = (const float*)d_in[14];
    const float* v2  = (const float*)d_in[15];
    float* out = (float*)d_out;

    cudaFuncSetAttribute(nn_kernel, cudaFuncAttributeMaxDynamicSharedMemorySize,
                         SPTS * (int)sizeof(float4));
    cudaFuncSetAttribute(fused_kernel, cudaFuncAttributeMaxDynamicSharedMemorySize,
                         SMEM_BYTES);

    prep_kernel<<<64, 256>>>(W1, b1, g1, be1, m1, v1, W2, b2, g2, be2, m2, v2);
    nn_kernel<<<dim3(NPTS / 256, BB), 256, SPTS * sizeof(float4)>>>(xyz1, xyz2);
    fused_kernel<<<dim3(NPTS / NPB, BB), NTHR, SMEM_BYTES>>>(feat1, feat2, out);
}

// round 12
// speedup vs baseline: 2.1968x; 1.0328x over previous
#include <cuda_runtime.h>
#include <cuda_bf16.h>
#include <cuda_fp16.h>
#include <cstdint>

// Problem constants
#define BB   4
#define NPTS 16384
#define SPTS 4096
#define C1   128
#define C2   256
#define CIN  384
#define H1   256
#define H2   128

#define NPB  64          // points per fused block
#define NTHR 256

// Row strides: k64 chunk rows = 64 fp16 = 128B + 16 pad = 144B
// (9 16B-granules, coprime 8 -> conflict-free ldmatrix)
// H1 rows = 256 fp16 = 512B + 16 pad = 528B (33 granules, coprime 8)
#define KST  144
#define H1SB 528

// Weight chunk sizes (one k64 chunk, fp16 single plane):
//   W1: 256 rows x 144B = 36864 ; W2: 128 rows x 144B = 18432
#define W1CB 36864
#define W2CB 18432

__device__ __align__(16) unsigned char g_W1f[6 * W1CB];   // fp16, BN-folded
__device__ __align__(16) unsigned char g_W2f[4 * W2CB];   // fp16, BN-folded
__device__ float g_b1f[H1];
__device__ float g_b2f[H2];
__device__ int   g_ni[BB * NPTS * 3];
__device__ float g_nw[BB * NPTS * 3];

// ---------------- helpers ----------------
__device__ __forceinline__ uint32_t smem_to_u32(const void* p) {
    uint32_t a;
    asm("{ .reg .u64 t; cvta.to.shared.u64 t, %1; cvt.u32.u64 %0, t; }" : "=r"(a) : "l"(p));
    return a;
}
__device__ __forceinline__ void ldsm4(uint32_t* r, uint32_t a) {
    asm volatile("ldmatrix.sync.aligned.m8n8.x4.shared.b16 {%0,%1,%2,%3}, [%4];"
                 : "=r"(r[0]), "=r"(r[1]), "=r"(r[2]), "=r"(r[3]) : "r"(a));
}
__device__ __forceinline__ void mma_f16(float* d, const uint32_t* a, const uint32_t* b) {
    asm volatile("mma.sync.aligned.m16n8k16.row.col.f32.f16.f16.f32 "
                 "{%0,%1,%2,%3}, {%4,%5,%6,%7}, {%8,%9}, {%0,%1,%2,%3};"
                 : "+f"(d[0]), "+f"(d[1]), "+f"(d[2]), "+f"(d[3])
                 : "r"(a[0]), "r"(a[1]), "r"(a[2]), "r"(a[3]), "r"(b[0]), "r"(b[1]));
}
__device__ __forceinline__ void cpa16(uint32_t dst, const void* src) {
    asm volatile("cp.async.cg.shared.global [%0], [%1], 16;" :: "r"(dst), "l"(src));
}
#define CP_COMMIT() asm volatile("cp.async.commit_group;" ::: "memory")
#define CP_WAIT0()  asm volatile("cp.async.wait_group 0;" ::: "memory")

__device__ __forceinline__ uint32_t packh2(float v0, float v1) {
    return (uint32_t)__half_as_ushort(__float2half_rn(v0)) |
           ((uint32_t)__half_as_ushort(__float2half_rn(v1)) << 16);
}

// ---------------- kernel A: fold BN, lay out fp16 weights (k64 chunks) -------------
__global__ void prep_kernel(const float* __restrict__ W1, const float* __restrict__ b1,
                            const float* __restrict__ g1, const float* __restrict__ be1,
                            const float* __restrict__ m1, const float* __restrict__ v1,
                            const float* __restrict__ W2, const float* __restrict__ b2,
                            const float* __restrict__ g2, const float* __restrict__ be2,
                            const float* __restrict__ m2, const float* __restrict__ v2) {
    int idx = blockIdx.x * blockDim.x + threadIdx.x;
    int stride = gridDim.x * blockDim.x;

    // W1 -> fp16, 6 k64 chunks of [256 rows][144B]
    for (int g = idx; g < 256 * 96; g += stride) {
        int o = g / 96, k0 = (g % 96) * 4;
        float a = g1[o] * rsqrtf(v1[o] + 1e-5f);
        float v0 = W1[o * CIN + k0 + 0] * a;
        float v1_ = W1[o * CIN + k0 + 1] * a;
        float v2_ = W1[o * CIN + k0 + 2] * a;
        float v3 = W1[o * CIN + k0 + 3] * a;
        uint2 H = make_uint2(packh2(v0, v1_), packh2(v2_, v3));
        int chunk = k0 >> 6, kc = k0 & 63;
        *(uint2*)(g_W1f + (size_t)chunk * W1CB + o * KST + kc * 2) = H;
    }
    // W2 -> fp16, 4 k64 chunks of [128 rows][144B]
    for (int g = idx; g < 128 * 64; g += stride) {
        int o = g / 64, k0 = (g % 64) * 4;
        float a = g2[o] * rsqrtf(v2[o] + 1e-5f);
        float v0 = W2[o * H1 + k0 + 0] * a;
        float v1_ = W2[o * H1 + k0 + 1] * a;
        float v2_ = W2[o * H1 + k0 + 2] * a;
        float v3 = W2[o * H1 + k0 + 3] * a;
        uint2 H = make_uint2(packh2(v0, v1_), packh2(v2_, v3));
        int chunk = k0 >> 6, kc = k0 & 63;
        *(uint2*)(g_W2f + (size_t)chunk * W2CB + o * KST + kc * 2) = H;
    }
    for (int o = idx; o < H1; o += stride) {
        float a = g1[o] * rsqrtf(v1[o] + 1e-5f);
        g_b1f[o] = (b1[o] - m1[o]) * a + be1[o];
    }
    for (int o = idx; o < H2; o += stride) {
        float a = g2[o] * rsqrtf(v2[o] + 1e-5f);
        g_b2f[o] = (b2[o] - m2[o]) * a + be2[o];
    }
}

// ---------------- kernel B: exact 3-NN + interpolation weights (unchanged) ----------
__global__ void __launch_bounds__(256) nn_kernel(const float* __restrict__ xyz1,
                                                 const float* __restrict__ xyz2) {
    extern __shared__ float4 sc[];
    const int b = blockIdx.y;
    const int n = blockIdx.x * 256 + threadIdx.x;

    const float* x2 = xyz2 + b * SPTS * 3;
    for (int s = threadIdx.x; s < SPTS; s += 256) {
        float x = x2[s * 3 + 0], y = x2[s * 3 + 1], z = x2[s * 3 + 2];
        sc[s] = make_float4(fmaf(x, x, fmaf(y, y, z * z)), -2.f * x, -2.f * y, -2.f * z);
    }
    __syncthreads();

    const float* qq = xyz1 + (b * NPTS + n) * 3;
    const float qx = qq[0], qy = qq[1], qz = qq[2];

    const float INF = __int_as_float(0x7f800000);
    float d0 = INF, d1 = INF, d2 = INF;
    int i0 = 0, i1 = 0, i2 = 0;

#pragma unroll 4
    for (int s = 0; s < SPTS; s++) {
        float4 c = sc[s];
        float t = fmaf(c.y, qx, c.x);
        t = fmaf(c.z, qy, t);
        t = fmaf(c.w, qz, t);
        if (t < d2) {
            if (t < d1) {
                d2 = d1; i2 = i1;
                if (t < d0) { d1 = d0; i1 = i0; d0 = t; i0 = s; }
                else        { d1 = t;  i1 = s; }
            } else { d2 = t; i2 = s; }
        }
    }

    const float qn = fmaf(qx, qx, fmaf(qy, qy, qz * qz));
    float r0 = 1.f / ((d0 + qn) + 1e-8f);
    float r1 = 1.f / ((d1 + qn) + 1e-8f);
    float r2 = 1.f / ((d2 + qn) + 1e-8f);
    float inv = 1.f / (r0 + r1 + r2);

    const int base = (b * NPTS + n) * 3;
    g_ni[base + 0] = i0; g_ni[base + 1] = i1; g_ni[base + 2] = i2;
    g_nw[base + 0] = r0 * inv; g_nw[base + 1] = r1 * inv; g_nw[base + 2] = r2 * inv;
}

// ---------------- kernel C: fp16x1 GEMM1 + fp16x1 GEMM2, k64 chunks, 2 blk/SM ------
// 64 points/block, 256 threads (8 warps).
// SMEM (bytes):
//  phase1: A1 bufs 2 x 9216 @0               .. 18432
//          B1 bufs 2 x 36864 @18432          .. 92160
//  phase2: H1 single plane @0 (33792)
//          B2 bufs 2 x 18432 @34816          .. 71680
#define A1_OFF  0
#define A1_BUF  9216
#define B1_OFF  18432
#define B1_BUF  36864
#define H1_OFF  0
#define B2_OFF  34816
#define B2_BUF  18432
#define SMEM_BYTES 92160

__global__ void __launch_bounds__(NTHR, 2) fused_kernel(const float* __restrict__ feat1,
                                                        const float* __restrict__ feat2,
                                                        float* __restrict__ out) {
    extern __shared__ __align__(128) char sm[];
    const uint32_t sb = smem_to_u32(sm);
    const int tid  = threadIdx.x;
    const int lane = tid & 31;
    const int wid  = tid >> 5;
    const int b    = blockIdx.y;
    const int n0g  = blockIdx.x * NPB;

    // producer mapping: 4 threads per point, 16 channels each per k64 chunk
    const int p = tid >> 2;
    const int q = tid & 3;
    const int nbase = (b * NPTS + n0g + p) * 3;
    const int j0 = g_ni[nbase], j1 = g_ni[nbase + 1], j2 = g_ni[nbase + 2];
    const float w0 = g_nw[nbase], w1 = g_nw[nbase + 1], w2 = g_nw[nbase + 2];

    // ldmatrix decomposition
    const int r8 = lane & 7;
    const int g4 = lane >> 3;
    const int gm = (g4 & 1) << 3;
    const int gk = (g4 >> 1) << 3;

    // warp tiles: GEMM1 M16xN128, GEMM2 M16xN64
    const int m0  = (wid >> 1) * 16;
    const int nh0 = (wid & 1) * 128;
    const int n20 = (wid & 1) * 64;

    float d1[16][4];
#pragma unroll
    for (int nt = 0; nt < 16; nt++)
#pragma unroll
        for (int i = 0; i < 4; i++) d1[nt][i] = 0.f;

    float4 pf0, pf1, pf2, pf3, pf4, pf5;

    // half h covers 8 channels: cl = q*16 + h*8
    auto ldg_part = [&](int nc, int h) {
        const int cl = q * 16 + h * 8;
        const int cg = nc * 64 + cl;
        if (cg < C1) {
            const float4* s4 = (const float4*)(feat1 + ((size_t)(b * NPTS + n0g + p)) * C1 + cg);
            pf0 = __ldg(s4); pf1 = __ldg(s4 + 1);
        } else {
            const int c2 = cg - C1;
            const float4* r0 = (const float4*)(feat2 + ((size_t)b * SPTS + j0) * C2 + c2);
            const float4* r1 = (const float4*)(feat2 + ((size_t)b * SPTS + j1) * C2 + c2);
            const float4* r2 = (const float4*)(feat2 + ((size_t)b * SPTS + j2) * C2 + c2);
            pf0 = __ldg(r0); pf1 = __ldg(r0 + 1);
            pf2 = __ldg(r1); pf3 = __ldg(r1 + 1);
            pf4 = __ldg(r2); pf5 = __ldg(r2 + 1);
        }
    };
    auto sts_part = [&](int nc, int h) {
        float v[8];
        if (nc * 64 + q * 16 + h * 8 < C1) {
            v[0] = pf0.x; v[1] = pf0.y; v[2] = pf0.z; v[3] = pf0.w;
            v[4] = pf1.x; v[5] = pf1.y; v[6] = pf1.z; v[7] = pf1.w;
        } else {
            v[0] = fmaf(w0, pf0.x, fmaf(w1, pf2.x, w2 * pf4.x));
            v[1] = fmaf(w0, pf0.y, fmaf(w1, pf2.y, w2 * pf4.y));
            v[2] = fmaf(w0, pf0.z, fmaf(w1, pf2.z, w2 * pf4.z));
            v[3] = fmaf(w0, pf0.w, fmaf(w1, pf2.w, w2 * pf4.w));
            v[4] = fmaf(w0, pf1.x, fmaf(w1, pf3.x, w2 * pf5.x));
            v[5] = fmaf(w0, pf1.y, fmaf(w1, pf3.y, w2 * pf5.y));
            v[6] = fmaf(w0, pf1.z, fmaf(w1, pf3.z, w2 * pf5.z));
            v[7] = fmaf(w0, pf1.w, fmaf(w1, pf3.w, w2 * pf5.w));
        }
        uint4 H = make_uint4(packh2(v[0], v[1]), packh2(v[2], v[3]),
                             packh2(v[4], v[5]), packh2(v[6], v[7]));
        *(uint4*)(sm + A1_OFF + (nc & 1) * A1_BUF + p * KST + (q * 16 + h * 8) * 2) = H;
    };
    auto consume1 = [&](uint32_t Au, uint32_t Bu, int ks) {
        uint32_t ah[4];
        ldsm4(ah, Au + (uint32_t)((m0 + r8 + gm) * KST + (ks * 16 + gk) * 2));
#pragma unroll
        for (int nb = 0; nb < 2; nb++) {
            uint32_t bbf[8][2];
#pragma unroll
            for (int np = 0; np < 4; np++)
                ldsm4(&bbf[2 * np][0],
                      Bu + (uint32_t)((nh0 + nb * 64 + np * 16 + r8 + gk) * KST
                                      + (ks * 16 + gm) * 2));
#pragma unroll
            for (int nt = 0; nt < 8; nt++) mma_f16(d1[nb * 8 + nt], ah, bbf[nt]);
        }
    };

    // ---- pre-loop: produce chunk 0 + cp.async W1 chunk 0 ----
    ldg_part(0, 0); sts_part(0, 0);
    ldg_part(0, 1); sts_part(0, 1);
    {
        const uint32_t dH = sb + B1_OFF;
        for (int i = tid * 16; i < W1CB; i += NTHR * 16)
            cpa16(dH + i, g_W1f + i);
        CP_COMMIT();
    }

    // ---- phase 1: 6 chunks of k64, fp16 single product ----
    for (int ci = 0; ci < 6; ci++) {
        const int s = ci & 1;
        const uint32_t Au = sb + A1_OFF + s * A1_BUF;
        const uint32_t Bu = sb + B1_OFF + s * B1_BUF;
        const int nc = ci + 1;

        CP_WAIT0();          // W1(ci) arrived (thread-local)
        __syncthreads();     // W1(ci)/A(ci) visible to all; consume(ci-1) done everywhere

        if (nc < 6) {        // prefetch weights for next chunk during this mma phase
            const unsigned char* srcW = g_W1f + (size_t)nc * W1CB;
            const uint32_t dH = sb + B1_OFF + (nc & 1) * B1_BUF;
            for (int i = tid * 16; i < W1CB; i += NTHR * 16)
                cpa16(dH + i, srcW + i);
            CP_COMMIT();
        }

        if (nc < 6) ldg_part(nc, 0);
        consume1(Au, Bu, 0);
        if (nc < 6) { sts_part(nc, 0); ldg_part(nc, 1); }
        consume1(Au, Bu, 1);
        consume1(Au, Bu, 2);
        if (nc < 6) sts_part(nc, 1);
        consume1(Au, Bu, 3);
    }
    __syncthreads();         // all consumes done before H1/B2 region overwrite

    // ---- prefetch W2 chunk 0, then epilogue1 (covers the cp.async) ----
    {
        const uint32_t dH = sb + B2_OFF;
        for (int i = tid * 16; i < W2CB; i += NTHR * 16)
            cpa16(dH + i, g_W2f + i);
        CP_COMMIT();
    }
    // epilogue1: bias + ReLU + fp16 -> H1 smem (single plane)
#pragma unroll
    for (int nt = 0; nt < 16; nt++) {
        const int col = nh0 + nt * 8 + (lane & 3) * 2;
        const float bb0 = __ldg(g_b1f + col), bb1 = __ldg(g_b1f + col + 1);
        const int row = m0 + (lane >> 2);
        *(uint32_t*)(sm + H1_OFF + row * H1SB + col * 2) =
            packh2(fmaxf(d1[nt][0] + bb0, 0.f), fmaxf(d1[nt][1] + bb1, 0.f));
        *(uint32_t*)(sm + H1_OFF + (row + 8) * H1SB + col * 2) =
            packh2(fmaxf(d1[nt][2] + bb0, 0.f), fmaxf(d1[nt][3] + bb1, 0.f));
    }

    // ---- phase 2: GEMM2, 4 chunks of k64, fp16 single product ----
    float d2[8][4];
#pragma unroll
    for (int nt = 0; nt < 8; nt++)
#pragma unroll
        for (int i = 0; i < 4; i++) d2[nt][i] = 0.f;

    for (int cj = 0; cj < 4; cj++) {
        const int s = cj & 1;
        const uint32_t Bu = sb + B2_OFF + s * B2_BUF;
        const int ncj = cj + 1;

        CP_WAIT0();          // W2(cj) arrived
        __syncthreads();     // also orders H1 writes (cj==0) and buffer reuse

        if (ncj < 4) {
            const unsigned char* srcW = g_W2f + (size_t)ncj * W2CB;
            const uint32_t dH = sb + B2_OFF + (ncj & 1) * B2_BUF;
            for (int i = tid * 16; i < W2CB; i += NTHR * 16)
                cpa16(dH + i, srcW + i);
            CP_COMMIT();
        }

#pragma unroll
        for (int ks = 0; ks < 4; ks++) {
            uint32_t ah[4];
            ldsm4(ah, sb + H1_OFF + (uint32_t)((m0 + r8 + gm) * H1SB
                                               + (cj * 64 + ks * 16 + gk) * 2));
            uint32_t bbf[8][2];
#pragma unroll
            for (int np = 0; np < 4; np++)
                ldsm4(&bbf[2 * np][0],
                      Bu + (uint32_t)((n20 + np * 16 + r8 + gk) * KST + (ks * 16 + gm) * 2));
#pragma unroll
            for (int nt = 0; nt < 8; nt++) mma_f16(d2[nt], ah, bbf[nt]);
        }
    }

    // ---- epilogue2: bias + ReLU -> fp32 out ----
#pragma unroll
    for (int nt = 0; nt < 8; nt++) {
        const int col = n20 + nt * 8 + (lane & 3) * 2;
        const float bb0 = __ldg(g_b2f + col), bb1 = __ldg(g_b2f + col + 1);
        const int row = m0 + (lane >> 2);
        float2 v0 = make_float2(fmaxf(d2[nt][0] + bb0, 0.f), fmaxf(d2[nt][1] + bb1, 0.f));
        float2 v1 = make_float2(fmaxf(d2[nt][2] + bb0, 0.f), fmaxf(d2[nt][3] + bb1, 0.f));
        *(float2*)(out + ((size_t)(b * NPTS + n0g + row)) * H2 + col) = v0;
        *(float2*)(out + ((size_t)(b * NPTS + n0g + row + 8)) * H2 + col) = v1;
    }
}

// ---------------- launch ----------------
extern "C" void kernel_launch(void* const* d_in, const int* in_sizes, int n_in,
                              void* d_out, int out_size) {
    const float* xyz1  = (const float*)d_in[0];
    const float* feat1 = (const float*)d_in[1];
    const float* xyz2  = (const float*)d_in[2];
    const float* feat2 = (const float*)d_in[3];
    const float* W1  = (const float*)d_in[4];
    const float* b1  = (const float*)d_in[5];
    const float* g1  = (const float*)d_in[6];
    const float* be1 = (const float*)d_in[7];
    const float* m1  = (const float*)d_in[8];
    const float* v1  = (const float*)d_in[9];
    const float* W2  = (const float*)d_in[10];
    const float* b2  = (const float*)d_in[11];
    const float* g2  = (const float*)d_in[12];
    const float* be2 = (const float*)d_in[13];
    const float* m2  = (const float*)d_in[14];
    const float* v2  = (const float*)d_in[15];
    float* out = (float*)d_out;

    cudaFuncSetAttribute(nn_kernel, cudaFuncAttributeMaxDynamicSharedMemorySize,
                         SPTS * (int)sizeof(float4));
    cudaFuncSetAttribute(fused_kernel, cudaFuncAttributeMaxDynamicSharedMemorySize,
                         SMEM_BYTES);

    prep_kernel<<<64, 256>>>(W1, b1, g1, be1, m1, v1, W2, b2, g2, be2, m2, v2);
    nn_kernel<<<dim3(NPTS / 256, BB), 256, SPTS * sizeof(float4)>>>(xyz1, xyz2);
    fused_kernel<<<dim3(NPTS / NPB, BB), NTHR, SMEM_BYTES>>>(feat1, feat2, out);
}

// round 13
// speedup vs baseline: 2.2136x; 1.0076x over previous
#include <cuda_runtime.h>
#include <cuda_bf16.h>
#include <cuda_fp16.h>
#include <cstdint>

// Problem constants
#define BB   4
#define NPTS 16384
#define SPTS 4096
#define C1   128
#define C2   256
#define CIN  384
#define H1   256
#define H2   128

#define NPB  64          // points per fused block
#define NTHR 512

// Row strides: k64 chunk rows = 64 fp16 = 128B + 16 pad = 144B
// (9 16B-granules, coprime 8 -> conflict-free ldmatrix)
// H1 rows = 256 fp16 = 512B + 16 pad = 528B (33 granules, coprime 8)
#define KST  144
#define H1SB 528

// Weight chunk sizes (one k64 chunk, fp16 single plane):
//   W1: 256 rows x 144B = 36864 ; W2: 128 rows x 144B = 18432
#define W1CB 36864
#define W2CB 18432

__device__ __align__(16) unsigned char g_W1f[6 * W1CB];   // fp16, BN-folded
__device__ __align__(16) unsigned char g_W2f[4 * W2CB];   // fp16, BN-folded
__device__ float g_b1f[H1];
__device__ float g_b2f[H2];
__device__ int   g_ni[BB * NPTS * 3];
__device__ float g_nw[BB * NPTS * 3];

// ---------------- helpers ----------------
__device__ __forceinline__ uint32_t smem_to_u32(const void* p) {
    uint32_t a;
    asm("{ .reg .u64 t; cvta.to.shared.u64 t, %1; cvt.u32.u64 %0, t; }" : "=r"(a) : "l"(p));
    return a;
}
__device__ __forceinline__ void ldsm4(uint32_t* r, uint32_t a) {
    asm volatile("ldmatrix.sync.aligned.m8n8.x4.shared.b16 {%0,%1,%2,%3}, [%4];"
                 : "=r"(r[0]), "=r"(r[1]), "=r"(r[2]), "=r"(r[3]) : "r"(a));
}
__device__ __forceinline__ void mma_f16(float* d, const uint32_t* a, const uint32_t* b) {
    asm volatile("mma.sync.aligned.m16n8k16.row.col.f32.f16.f16.f32 "
                 "{%0,%1,%2,%3}, {%4,%5,%6,%7}, {%8,%9}, {%0,%1,%2,%3};"
                 : "+f"(d[0]), "+f"(d[1]), "+f"(d[2]), "+f"(d[3])
                 : "r"(a[0]), "r"(a[1]), "r"(a[2]), "r"(a[3]), "r"(b[0]), "r"(b[1]));
}
__device__ __forceinline__ void cpa16(uint32_t dst, const void* src) {
    asm volatile("cp.async.cg.shared.global [%0], [%1], 16;" :: "r"(dst), "l"(src));
}
#define CP_COMMIT() asm volatile("cp.async.commit_group;" ::: "memory")
#define CP_WAIT0()  asm volatile("cp.async.wait_group 0;" ::: "memory")

__device__ __forceinline__ uint32_t packh2(float v0, float v1) {
    return (uint32_t)__half_as_ushort(__float2half_rn(v0)) |
           ((uint32_t)__half_as_ushort(__float2half_rn(v1)) << 16);
}

// ---------------- kernel A: fold BN, lay out fp16 weights (k64 chunks) -------------
__global__ void prep_kernel(const float* __restrict__ W1, const float* __restrict__ b1,
                            const float* __restrict__ g1, const float* __restrict__ be1,
                            const float* __restrict__ m1, const float* __restrict__ v1,
                            const float* __restrict__ W2, const float* __restrict__ b2,
                            const float* __restrict__ g2, const float* __restrict__ be2,
                            const float* __restrict__ m2, const float* __restrict__ v2) {
    int idx = blockIdx.x * blockDim.x + threadIdx.x;
    int stride = gridDim.x * blockDim.x;

    // W1 -> fp16, 6 k64 chunks of [256 rows][144B]
    for (int g = idx; g < 256 * 96; g += stride) {
        int o = g / 96, k0 = (g % 96) * 4;
        float a = g1[o] * rsqrtf(v1[o] + 1e-5f);
        float v0 = W1[o * CIN + k0 + 0] * a;
        float v1_ = W1[o * CIN + k0 + 1] * a;
        float v2_ = W1[o * CIN + k0 + 2] * a;
        float v3 = W1[o * CIN + k0 + 3] * a;
        uint2 H = make_uint2(packh2(v0, v1_), packh2(v2_, v3));
        int chunk = k0 >> 6, kc = k0 & 63;
        *(uint2*)(g_W1f + (size_t)chunk * W1CB + o * KST + kc * 2) = H;
    }
    // W2 -> fp16, 4 k64 chunks of [128 rows][144B]
    for (int g = idx; g < 128 * 64; g += stride) {
        int o = g / 64, k0 = (g % 64) * 4;
        float a = g2[o] * rsqrtf(v2[o] + 1e-5f);
        float v0 = W2[o * H1 + k0 + 0] * a;
        float v1_ = W2[o * H1 + k0 + 1] * a;
        float v2_ = W2[o * H1 + k0 + 2] * a;
        float v3 = W2[o * H1 + k0 + 3] * a;
        uint2 H = make_uint2(packh2(v0, v1_), packh2(v2_, v3));
        int chunk = k0 >> 6, kc = k0 & 63;
        *(uint2*)(g_W2f + (size_t)chunk * W2CB + o * KST + kc * 2) = H;
    }
    for (int o = idx; o < H1; o += stride) {
        float a = g1[o] * rsqrtf(v1[o] + 1e-5f);
        g_b1f[o] = (b1[o] - m1[o]) * a + be1[o];
    }
    for (int o = idx; o < H2; o += stride) {
        float a = g2[o] * rsqrtf(v2[o] + 1e-5f);
        g_b2f[o] = (b2[o] - m2[o]) * a + be2[o];
    }
}

// ---------------- kernel B: exact 3-NN + interpolation weights (unchanged) ----------
__global__ void __launch_bounds__(256) nn_kernel(const float* __restrict__ xyz1,
                                                 const float* __restrict__ xyz2) {
    extern __shared__ float4 sc[];
    const int b = blockIdx.y;
    const int n = blockIdx.x * 256 + threadIdx.x;

    const float* x2 = xyz2 + b * SPTS * 3;
    for (int s = threadIdx.x; s < SPTS; s += 256) {
        float x = x2[s * 3 + 0], y = x2[s * 3 + 1], z = x2[s * 3 + 2];
        sc[s] = make_float4(fmaf(x, x, fmaf(y, y, z * z)), -2.f * x, -2.f * y, -2.f * z);
    }
    __syncthreads();

    const float* qq = xyz1 + (b * NPTS + n) * 3;
    const float qx = qq[0], qy = qq[1], qz = qq[2];

    const float INF = __int_as_float(0x7f800000);
    float d0 = INF, d1 = INF, d2 = INF;
    int i0 = 0, i1 = 0, i2 = 0;

#pragma unroll 4
    for (int s = 0; s < SPTS; s++) {
        float4 c = sc[s];
        float t = fmaf(c.y, qx, c.x);
        t = fmaf(c.z, qy, t);
        t = fmaf(c.w, qz, t);
        if (t < d2) {
            if (t < d1) {
                d2 = d1; i2 = i1;
                if (t < d0) { d1 = d0; i1 = i0; d0 = t; i0 = s; }
                else        { d1 = t;  i1 = s; }
            } else { d2 = t; i2 = s; }
        }
    }

    const float qn = fmaf(qx, qx, fmaf(qy, qy, qz * qz));
    float r0 = 1.f / ((d0 + qn) + 1e-8f);
    float r1 = 1.f / ((d1 + qn) + 1e-8f);
    float r2 = 1.f / ((d2 + qn) + 1e-8f);
    float inv = 1.f / (r0 + r1 + r2);

    const int base = (b * NPTS + n) * 3;
    g_ni[base + 0] = i0; g_ni[base + 1] = i1; g_ni[base + 2] = i2;
    g_nw[base + 0] = r0 * inv; g_nw[base + 1] = r1 * inv; g_nw[base + 2] = r2 * inv;
}

// ---------------- kernel C: fp16 GEMMs, k64 chunks, 512 thr, 2 blk/SM --------------
// 64 points/block, 512 threads (16 warps), 50% occupancy.
// SMEM (bytes):
//  phase1: A1 bufs 2 x 9216 @0               .. 18432
//          B1 bufs 2 x 36864 @18432          .. 92160
//  phase2: H1 single plane @0 (33792)
//          B2 bufs 2 x 18432 @34816          .. 71680
#define A1_OFF  0
#define A1_BUF  9216
#define B1_OFF  18432
#define B1_BUF  36864
#define H1_OFF  0
#define B2_OFF  34816
#define B2_BUF  18432
#define SMEM_BYTES 92160

__global__ void __launch_bounds__(NTHR, 2) fused_kernel(const float* __restrict__ feat1,
                                                        const float* __restrict__ feat2,
                                                        float* __restrict__ out) {
    extern __shared__ __align__(128) char sm[];
    const uint32_t sb = smem_to_u32(sm);
    const int tid  = threadIdx.x;
    const int lane = tid & 31;
    const int wid  = tid >> 5;
    const int b    = blockIdx.y;
    const int n0g  = blockIdx.x * NPB;

    // producer mapping: 8 threads per point, 8 channels each per k64 chunk
    const int p = tid >> 3;
    const int q = tid & 7;
    const int nbase = (b * NPTS + n0g + p) * 3;
    const int j0 = g_ni[nbase], j1 = g_ni[nbase + 1], j2 = g_ni[nbase + 2];
    const float w0 = g_nw[nbase], w1 = g_nw[nbase + 1], w2 = g_nw[nbase + 2];

    // ldmatrix decomposition
    const int r8 = lane & 7;
    const int g4 = lane >> 3;
    const int gm = (g4 & 1) << 3;
    const int gk = (g4 >> 1) << 3;

    // warp tiles: GEMM1 M16xN64 (4x4 warp grid), GEMM2 M16xN32
    const int m0  = (wid >> 2) * 16;
    const int nh0 = (wid & 3) * 64;
    const int n20 = (wid & 3) * 32;

    float d1[8][4];
#pragma unroll
    for (int nt = 0; nt < 8; nt++)
#pragma unroll
        for (int i = 0; i < 4; i++) d1[nt][i] = 0.f;

    // produce 8 channels (2 x 4) of chunk nc into buffer nc&1
    auto produce = [&](int nc) {
        char* dst = sm + A1_OFF + (nc & 1) * A1_BUF + p * KST + q * 16;
#pragma unroll
        for (int h = 0; h < 2; h++) {
            const int cg = nc * 64 + q * 8 + h * 4;
            float v0, v1, v2, v3;
            if (cg < C1) {
                float4 x = __ldg((const float4*)(feat1
                              + ((size_t)(b * NPTS + n0g + p)) * C1 + cg));
                v0 = x.x; v1 = x.y; v2 = x.z; v3 = x.w;
            } else {
                const int c2 = cg - C1;
                float4 a0 = __ldg((const float4*)(feat2 + ((size_t)b * SPTS + j0) * C2 + c2));
                float4 b0 = __ldg((const float4*)(feat2 + ((size_t)b * SPTS + j1) * C2 + c2));
                float4 c0 = __ldg((const float4*)(feat2 + ((size_t)b * SPTS + j2) * C2 + c2));
                v0 = fmaf(w0, a0.x, fmaf(w1, b0.x, w2 * c0.x));
                v1 = fmaf(w0, a0.y, fmaf(w1, b0.y, w2 * c0.y));
                v2 = fmaf(w0, a0.z, fmaf(w1, b0.z, w2 * c0.z));
                v3 = fmaf(w0, a0.w, fmaf(w1, b0.w, w2 * c0.w));
            }
            *(uint2*)(dst + h * 8) = make_uint2(packh2(v0, v1), packh2(v2, v3));
        }
    };
    auto consume1 = [&](uint32_t Au, uint32_t Bu, int ks) {
        uint32_t ah[4];
        ldsm4(ah, Au + (uint32_t)((m0 + r8 + gm) * KST + (ks * 16 + gk) * 2));
#pragma unroll
        for (int nb = 0; nb < 2; nb++) {
            uint32_t bbf[4][2];
#pragma unroll
            for (int np = 0; np < 2; np++)
                ldsm4(&bbf[2 * np][0],
                      Bu + (uint32_t)((nh0 + nb * 32 + np * 16 + r8 + gk) * KST
                                      + (ks * 16 + gm) * 2));
#pragma unroll
            for (int nt = 0; nt < 4; nt++) mma_f16(d1[nb * 4 + nt], ah, bbf[nt]);
        }
    };

    // ---- pre-loop: produce chunk 0 + cp.async W1 chunk 0 ----
    produce(0);
    {
        const uint32_t dH = sb + B1_OFF;
        for (int i = tid * 16; i < W1CB; i += NTHR * 16)
            cpa16(dH + i, g_W1f + i);
        CP_COMMIT();
    }

    // ---- phase 1: 6 chunks of k64, fp16 single product ----
    for (int ci = 0; ci < 6; ci++) {
        const int s = ci & 1;
        const uint32_t Au = sb + A1_OFF + s * A1_BUF;
        const uint32_t Bu = sb + B1_OFF + s * B1_BUF;
        const int nc = ci + 1;

        CP_WAIT0();          // W1(ci) arrived (thread-local)
        __syncthreads();     // W1(ci)/A(ci) visible to all; consume(ci-1) done everywhere

        if (nc < 6) {        // prefetch weights for next chunk during this mma phase
            const unsigned char* srcW = g_W1f + (size_t)nc * W1CB;
            const uint32_t dH = sb + B1_OFF + (nc & 1) * B1_BUF;
            for (int i = tid * 16; i < W1CB; i += NTHR * 16)
                cpa16(dH + i, srcW + i);
            CP_COMMIT();
            produce(nc);     // A(ci+1) -> other buffer (its consume finished before top barrier)
        }

        consume1(Au, Bu, 0);
        consume1(Au, Bu, 1);
        consume1(Au, Bu, 2);
        consume1(Au, Bu, 3);
    }
    __syncthreads();         // all consumes done before H1/B2 region overwrite

    // ---- prefetch W2 chunk 0, then epilogue1 (covers the cp.async) ----
    {
        const uint32_t dH = sb + B2_OFF;
        for (int i = tid * 16; i < W2CB; i += NTHR * 16)
            cpa16(dH + i, g_W2f + i);
        CP_COMMIT();
    }
    // epilogue1: bias + ReLU + fp16 -> H1 smem (single plane)
#pragma unroll
    for (int nt = 0; nt < 8; nt++) {
        const int col = nh0 + nt * 8 + (lane & 3) * 2;
        const float bb0 = __ldg(g_b1f + col), bb1 = __ldg(g_b1f + col + 1);
        const int row = m0 + (lane >> 2);
        *(uint32_t*)(sm + H1_OFF + row * H1SB + col * 2) =
            packh2(fmaxf(d1[nt][0] + bb0, 0.f), fmaxf(d1[nt][1] + bb1, 0.f));
        *(uint32_t*)(sm + H1_OFF + (row + 8) * H1SB + col * 2) =
            packh2(fmaxf(d1[nt][2] + bb0, 0.f), fmaxf(d1[nt][3] + bb1, 0.f));
    }

    // ---- phase 2: GEMM2, 4 chunks of k64, fp16 single product ----
    float d2[4][4];
#pragma unroll
    for (int nt = 0; nt < 4; nt++)
#pragma unroll
        for (int i = 0; i < 4; i++) d2[nt][i] = 0.f;

    for (int cj = 0; cj < 4; cj++) {
        const int s = cj & 1;
        const uint32_t Bu = sb + B2_OFF + s * B2_BUF;
        const int ncj = cj + 1;

        CP_WAIT0();          // W2(cj) arrived
        __syncthreads();     // also orders H1 writes (cj==0) and buffer reuse

        if (ncj < 4) {
            const unsigned char* srcW = g_W2f + (size_t)ncj * W2CB;
            const uint32_t dH = sb + B2_OFF + (ncj & 1) * B2_BUF;
            for (int i = tid * 16; i < W2CB; i += NTHR * 16)
                cpa16(dH + i, srcW + i);
            CP_COMMIT();
        }

#pragma unroll
        for (int ks = 0; ks < 4; ks++) {
            uint32_t ah[4];
            ldsm4(ah, sb + H1_OFF + (uint32_t)((m0 + r8 + gm) * H1SB
                                               + (cj * 64 + ks * 16 + gk) * 2));
            uint32_t bbf[4][2];
#pragma unroll
            for (int np = 0; np < 2; np++)
                ldsm4(&bbf[2 * np][0],
                      Bu + (uint32_t)((n20 + np * 16 + r8 + gk) * KST + (ks * 16 + gm) * 2));
#pragma unroll
            for (int nt = 0; nt < 4; nt++) mma_f16(d2[nt], ah, bbf[nt]);
        }
    }

    // ---- epilogue2: bias + ReLU -> fp32 out ----
#pragma unroll
    for (int nt = 0; nt < 4; nt++) {
        const int col = n20 + nt * 8 + (lane & 3) * 2;
        const float bb0 = __ldg(g_b2f + col), bb1 = __ldg(g_b2f + col + 1);
        const int row = m0 + (lane >> 2);
        float2 v0 = make_float2(fmaxf(d2[nt][0] + bb0, 0.f), fmaxf(d2[nt][1] + bb1, 0.f));
        float2 v1 = make_float2(fmaxf(d2[nt][2] + bb0, 0.f), fmaxf(d2[nt][3] + bb1, 0.f));
        *(float2*)(out + ((size_t)(b * NPTS + n0g + row)) * H2 + col) = v0;
        *(float2*)(out + ((size_t)(b * NPTS + n0g + row + 8)) * H2 + col) = v1;
    }
}

// ---------------- launch ----------------
extern "C" void kernel_launch(void* const* d_in, const int* in_sizes, int n_in,
                              void* d_out, int out_size) {
    const float* xyz1  = (const float*)d_in[0];
    const float* feat1 = (const float*)d_in[1];
    const float* xyz2  = (const float*)d_in[2];
    const float* feat2 = (const float*)d_in[3];
    const float* W1  = (const float*)d_in[4];
    const float* b1  = (const float*)d_in[5];
    const float* g1  = (const float*)d_in[6];
    const float* be1 = (const float*)d_in[7];
    const float* m1  = (const float*)d_in[8];
    const float* v1  = (const float*)d_in[9];
    const float* W2  = (const float*)d_in[10];
    const float* b2  = (const float*)d_in[11];
    const float* g2  = (const float*)d_in[12];
    const float* be2 = (const float*)d_in[13];
    const float* m2  = (const float*)d_in[14];
    const float* v2  = (const float*)d_in[15];
    float* out = (float*)d_out;

    cudaFuncSetAttribute(nn_kernel, cudaFuncAttributeMaxDynamicSharedMemorySize,
                         SPTS * (int)sizeof(float4));
    cudaFuncSetAttribute(fused_kernel, cudaFuncAttributeMaxDynamicSharedMemorySize,
                         SMEM_BYTES);

    prep_kernel<<<64, 256>>>(W1, b1, g1, be1, m1, v1, W2, b2, g2, be2, m2, v2);
    nn_kernel<<<dim3(NPTS / 256, BB), 256, SPTS * sizeof(float4)>>>(xyz1, xyz2);
    fused_kernel<<<dim3(NPTS / NPB, BB), NTHR, SMEM_BYTES>>>(feat1, feat2, out);
}